// round 1
// baseline (speedup 1.0000x reference)
#include <cuda_runtime.h>
#include <math.h>

#define F 128
#define TA 8

__global__ void zero_out_kernel(float* out, int n) {
    int i = blockIdx.x * blockDim.x + threadIdx.x;
    if (i < n) out[i] = 0.0f;
}

__global__ void __launch_bounds__(128) fused_kernel(
    const float* __restrict__ s_in, const float* __restrict__ v_in,
    const float* __restrict__ mask,
    const float* __restrict__ w1, const float* __restrict__ w2,
    const float* __restrict__ a1w, const float* __restrict__ a1b,
    const float* __restrict__ a2w, const float* __restrict__ a2b,
    const float* __restrict__ out_w, const float* __restrict__ out_b,
    float* __restrict__ out,
    int n_atoms, int n_graphs, int n_layers)
{
    const int g = threadIdx.x;              // feature index (0..127)
    const int atom0 = blockIdx.x * TA;
    const int na = min(TA, n_atoms - atom0);

    __shared__ float sv[TA][3][F];   // vector features (updated per layer)
    __shared__ float ss[TA][F];      // scalar features (updated per layer)
    __shared__ float hb[TA][2 * F];  // concat / activation buffer
    __shared__ float red[TA][4];     // warp reduction partials
    __shared__ float scs[TA];        // per-atom scalar output

    // ---- load tiles (zero-fill inactive atom slots) ----
    #pragma unroll
    for (int a = 0; a < TA; a++) {
        if (a < na) {
            ss[a][g] = s_in[(size_t)(atom0 + a) * F + g];
            #pragma unroll
            for (int c = 0; c < 3; c++)
                sv[a][c][g] = v_in[((size_t)(atom0 + a) * 3 + c) * F + g];
        } else {
            ss[a][g] = 0.0f;
            #pragma unroll
            for (int c = 0; c < 3; c++) sv[a][c][g] = 0.0f;
        }
    }
    __syncthreads();

    for (int l = 0; l < n_layers; l++) {
        const float* W1 = w1 + (size_t)l * F * F;
        const float* W2 = w2 + (size_t)l * F * F;
        const float* A1 = a1w + (size_t)l * 2 * F * F;
        const float* A2 = a2w + (size_t)l * F * 2 * F;

        // ---- combined v1 = v@W1, v2 = v@W2 pass (thread g = output column g) ----
        float acc1[TA][3];  // v1 (kept live until gating)
        float acc2[TA][3];  // v2 (collapsed into norm right after)
        #pragma unroll
        for (int a = 0; a < TA; a++)
            #pragma unroll
            for (int c = 0; c < 3; c++) { acc1[a][c] = 0.0f; acc2[a][c] = 0.0f; }

        #pragma unroll 4
        for (int f = 0; f < F; f++) {
            float wa = W1[f * F + g];
            float wb = W2[f * F + g];
            #pragma unroll
            for (int a = 0; a < TA; a++) {
                #pragma unroll
                for (int c = 0; c < 3; c++) {
                    float vv = sv[a][c][f];
                    acc1[a][c] = fmaf(vv, wa, acc1[a][c]);
                    acc2[a][c] = fmaf(vv, wb, acc2[a][c]);
                }
            }
        }

        // ---- n2 = ||v2|| over spatial, build concat h = [s, n2] ----
        #pragma unroll
        for (int a = 0; a < TA; a++) {
            float n2 = sqrtf(acc2[a][0] * acc2[a][0] +
                             acc2[a][1] * acc2[a][1] +
                             acc2[a][2] * acc2[a][2]);
            hb[a][g] = ss[a][g];
            hb[a][F + g] = n2;
        }
        __syncthreads();

        // ---- act = silu(h @ A1 + b1) ----
        float act[TA];
        #pragma unroll
        for (int a = 0; a < TA; a++) act[a] = 0.0f;
        #pragma unroll 4
        for (int f = 0; f < 2 * F; f++) {
            float wv = A1[f * F + g];
            #pragma unroll
            for (int a = 0; a < TA; a++)
                act[a] = fmaf(hb[a][f], wv, act[a]);
        }
        {
            float b = a1b[l * F + g];
            #pragma unroll
            for (int a = 0; a < TA; a++) {
                float x = act[a] + b;
                act[a] = x / (1.0f + expf(-x));   // silu
            }
        }
        __syncthreads();                 // all hb reads done
        #pragma unroll
        for (int a = 0; a < TA; a++) hb[a][g] = act[a];
        __syncthreads();

        // ---- h2 = act @ A2 + b2 ; split into s_out (first F) and gate (second F) ----
        float so[TA], ga[TA];
        #pragma unroll
        for (int a = 0; a < TA; a++) { so[a] = 0.0f; ga[a] = 0.0f; }
        #pragma unroll 4
        for (int f = 0; f < F; f++) {
            float wA = A2[f * 2 * F + g];
            float wB = A2[f * 2 * F + F + g];
            #pragma unroll
            for (int a = 0; a < TA; a++) {
                float h = hb[a][f];
                so[a] = fmaf(h, wA, so[a]);
                ga[a] = fmaf(h, wB, ga[a]);
            }
        }
        {
            float bA = a2b[l * 2 * F + g];
            float bB = a2b[l * 2 * F + F + g];
            #pragma unroll
            for (int a = 0; a < TA; a++) { so[a] += bA; ga[a] += bB; }
        }

        // ---- write back s_out, v_out = gate * v1 ----
        __syncthreads();                 // all sv reads (v-pass) + hb reads done
        #pragma unroll
        for (int a = 0; a < TA; a++) {
            ss[a][g] = so[a];
            #pragma unroll
            for (int c = 0; c < 3; c++)
                sv[a][c][g] = ga[a] * acc1[a][c];
        }
        __syncthreads();
    }

    // ---- sc = s @ out_w + out_b  (reduce over feature dim) ----
    {
        float ow = out_w[g];
        float p[TA];
        #pragma unroll
        for (int a = 0; a < TA; a++) p[a] = ss[a][g] * ow;
        #pragma unroll
        for (int off = 16; off > 0; off >>= 1) {
            #pragma unroll
            for (int a = 0; a < TA; a++)
                p[a] += __shfl_xor_sync(0xffffffff, p[a], off);
        }
        int lane = g & 31, warp = g >> 5;
        if (lane == 0) {
            #pragma unroll
            for (int a = 0; a < TA; a++) red[a][warp] = p[a];
        }
        __syncthreads();
        if (g < TA)
            scs[g] = red[g][0] + red[g][1] + red[g][2] + red[g][3] + out_b[0];
        __syncthreads();
    }

    // ---- masked segment sum: thread b accumulates its graph over this tile ----
    for (int b = g; b < n_graphs; b += blockDim.x) {
        float acc = 0.0f;
        const float* mrow = mask + (size_t)b * n_atoms + atom0;
        for (int a = 0; a < na; a++)
            acc = fmaf(scs[a], mrow[a], acc);
        atomicAdd(&out[b], acc);
    }
}

extern "C" void kernel_launch(void* const* d_in, const int* in_sizes, int n_in,
                              void* d_out, int out_size) {
    const float* s    = (const float*)d_in[0];
    const float* v    = (const float*)d_in[1];
    // d_in[2] = r (unused when dy=False)
    const float* mask = (const float*)d_in[3];
    const float* w1   = (const float*)d_in[4];
    const float* w2   = (const float*)d_in[5];
    const float* a1w  = (const float*)d_in[6];
    const float* a1b  = (const float*)d_in[7];
    const float* a2w  = (const float*)d_in[8];
    const float* a2b  = (const float*)d_in[9];
    const float* ow   = (const float*)d_in[10];
    const float* ob   = (const float*)d_in[11];
    float* out = (float*)d_out;

    int n_atoms  = in_sizes[0] / F;       // s is (1, N, F)
    int n_graphs = out_size;              // output is (B, 1)
    int n_layers = in_sizes[7] / F;       // a1b is (L, F)

    zero_out_kernel<<<(out_size + 127) / 128, 128>>>(out, out_size);

    int grid = (n_atoms + TA - 1) / TA;
    fused_kernel<<<grid, 128>>>(s, v, mask, w1, w2, a1w, a1b, a2w, a2b,
                                ow, ob, out, n_atoms, n_graphs, n_layers);
}

// round 2
// speedup vs baseline: 1.3587x; 1.3587x over previous
#include <cuda_runtime.h>
#include <math.h>

#define F 128
#define TA 8
#define NP 4   // atom pairs

typedef unsigned long long ull;

__device__ __forceinline__ ull dup2(float w) {
    ull r;
    asm("mov.b64 %0, {%1, %1};" : "=l"(r) : "f"(w));
    return r;
}
__device__ __forceinline__ ull pack2(float lo, float hi) {
    ull r;
    asm("mov.b64 %0, {%1, %2};" : "=l"(r) : "f"(lo), "f"(hi));
    return r;
}
__device__ __forceinline__ void unpack2(ull u, float& lo, float& hi) {
    asm("mov.b64 {%0, %1}, %2;" : "=f"(lo), "=f"(hi) : "l"(u));
}
__device__ __forceinline__ void ffma2(ull& a, ull v, ull w) {
    asm("fma.rn.f32x2 %0, %1, %2, %0;" : "+l"(a) : "l"(v), "l"(w));
}
__device__ __forceinline__ ull fmul2(ull v, ull w) {
    ull r;
    asm("mul.rn.f32x2 %0, %1, %2;" : "=l"(r) : "l"(v), "l"(w));
    return r;
}
__device__ __forceinline__ ull fadd2(ull v, ull w) {
    ull r;
    asm("add.rn.f32x2 %0, %1, %2;" : "=l"(r) : "l"(v), "l"(w));
    return r;
}

__global__ void zero_out_kernel(float* out, int n) {
    int i = blockIdx.x * blockDim.x + threadIdx.x;
    if (i < n) out[i] = 0.0f;
}

__global__ void __launch_bounds__(128) fused_kernel(
    const float* __restrict__ s_in, const float* __restrict__ v_in,
    const float* __restrict__ mask,
    const float* __restrict__ w1, const float* __restrict__ w2,
    const float* __restrict__ a1w, const float* __restrict__ a1b,
    const float* __restrict__ a2w, const float* __restrict__ a2b,
    const float* __restrict__ out_w, const float* __restrict__ out_b,
    float* __restrict__ out,
    int n_atoms, int n_graphs, int n_layers)
{
    const int g = threadIdx.x;              // feature index (0..127)
    const int atom0 = blockIdx.x * TA;
    const int na = min(TA, n_atoms - atom0);

    // atom-major tiles: last dim = atom -> packed f32x2 over atom pairs
    __shared__ float svT[3][F][TA];      // 12 KB vector features
    __shared__ float hbT[2 * F][TA];     // 8 KB  concat [s ; n2] / activations
    __shared__ float red[TA][4];
    __shared__ float scs[TA];

    // ---- load tiles (zero-fill inactive atom slots) ----
    #pragma unroll
    for (int a = 0; a < TA; a++) {
        float sval = 0.0f, v0 = 0.0f, v1 = 0.0f, v2 = 0.0f;
        if (a < na) {
            size_t base = (size_t)(atom0 + a);
            sval = s_in[base * F + g];
            v0 = v_in[(base * 3 + 0) * F + g];
            v1 = v_in[(base * 3 + 1) * F + g];
            v2 = v_in[(base * 3 + 2) * F + g];
        }
        hbT[g][a] = sval;
        svT[0][g][a] = v0;
        svT[1][g][a] = v1;
        svT[2][g][a] = v2;
    }
    __syncthreads();

    for (int l = 0; l < n_layers; l++) {
        const float* W1 = w1 + (size_t)l * F * F;
        const float* W2 = w2 + (size_t)l * F * F;
        const float* A1 = a1w + (size_t)l * 2 * F * F;
        const float* A2 = a2w + (size_t)l * F * 2 * F;

        // ---- v1 = v@W1, v2 = v@W2 (thread g = output column g, packed atom pairs) ----
        ull acc1[3][NP], acc2[3][NP];
        #pragma unroll
        for (int c = 0; c < 3; c++)
            #pragma unroll
            for (int p = 0; p < NP; p++) { acc1[c][p] = 0ull; acc2[c][p] = 0ull; }

        #pragma unroll 4
        for (int f = 0; f < F; f++) {
            ull uw1 = dup2(W1[f * F + g]);
            ull uw2 = dup2(W2[f * F + g]);
            #pragma unroll
            for (int c = 0; c < 3; c++) {
                ulonglong2 lo = *(const ulonglong2*)&svT[c][f][0];  // atoms 0-3
                ulonglong2 hi = *(const ulonglong2*)&svT[c][f][4];  // atoms 4-7
                ffma2(acc1[c][0], lo.x, uw1); ffma2(acc2[c][0], lo.x, uw2);
                ffma2(acc1[c][1], lo.y, uw1); ffma2(acc2[c][1], lo.y, uw2);
                ffma2(acc1[c][2], hi.x, uw1); ffma2(acc2[c][2], hi.x, uw2);
                ffma2(acc1[c][3], hi.y, uw1); ffma2(acc2[c][3], hi.y, uw2);
            }
        }

        // ---- n2 = ||v2|| over spatial; h = [s(already in hbT[0:F]), n2] ----
        #pragma unroll
        for (int p = 0; p < NP; p++) {
            ull sq = fmul2(acc2[0][p], acc2[0][p]);
            ffma2(sq, acc2[1][p], acc2[1][p]);
            ffma2(sq, acc2[2][p], acc2[2][p]);
            float q0, q1; unpack2(sq, q0, q1);
            *(ull*)&hbT[F + g][2 * p] = pack2(sqrtf(q0), sqrtf(q1));
        }
        __syncthreads();

        // ---- act = silu(h @ A1 + b1) ----
        ull acc[NP];
        #pragma unroll
        for (int p = 0; p < NP; p++) acc[p] = 0ull;
        #pragma unroll 4
        for (int f = 0; f < 2 * F; f++) {
            ull uw = dup2(A1[f * F + g]);
            ulonglong2 lo = *(const ulonglong2*)&hbT[f][0];
            ulonglong2 hi = *(const ulonglong2*)&hbT[f][4];
            ffma2(acc[0], lo.x, uw);
            ffma2(acc[1], lo.y, uw);
            ffma2(acc[2], hi.x, uw);
            ffma2(acc[3], hi.y, uw);
        }
        {
            float b = a1b[l * F + g];
            #pragma unroll
            for (int p = 0; p < NP; p++) {
                float x0, x1; unpack2(acc[p], x0, x1);
                x0 += b; x1 += b;
                x0 = x0 / (1.0f + expf(-x0));
                x1 = x1 / (1.0f + expf(-x1));
                acc[p] = pack2(x0, x1);
            }
        }
        __syncthreads();                 // all hbT reads done before overwrite
        #pragma unroll
        for (int p = 0; p < NP; p++)
            *(ull*)&hbT[g][2 * p] = acc[p];
        __syncthreads();

        // ---- h2 = act @ A2 + b2 ; first F -> s_out, second F -> gate ----
        ull aso[NP], aga[NP];
        #pragma unroll
        for (int p = 0; p < NP; p++) { aso[p] = 0ull; aga[p] = 0ull; }
        #pragma unroll 4
        for (int f = 0; f < F; f++) {
            ull uwA = dup2(A2[f * 2 * F + g]);
            ull uwB = dup2(A2[f * 2 * F + F + g]);
            ulonglong2 lo = *(const ulonglong2*)&hbT[f][0];
            ulonglong2 hi = *(const ulonglong2*)&hbT[f][4];
            ffma2(aso[0], lo.x, uwA); ffma2(aga[0], lo.x, uwB);
            ffma2(aso[1], lo.y, uwA); ffma2(aga[1], lo.y, uwB);
            ffma2(aso[2], hi.x, uwA); ffma2(aga[2], hi.x, uwB);
            ffma2(aso[3], hi.y, uwA); ffma2(aga[3], hi.y, uwB);
        }
        {
            ull ubA = dup2(a2b[l * 2 * F + g]);
            ull ubB = dup2(a2b[l * 2 * F + F + g]);
            #pragma unroll
            for (int p = 0; p < NP; p++) {
                aso[p] = fadd2(aso[p], ubA);
                aga[p] = fadd2(aga[p], ubB);
            }
        }

        __syncthreads();                 // all hbT/svT reads done before overwrite
        #pragma unroll
        for (int p = 0; p < NP; p++) {
            *(ull*)&hbT[g][2 * p] = aso[p];          // s for next layer
            #pragma unroll
            for (int c = 0; c < 3; c++)
                *(ull*)&svT[c][g][2 * p] = fmul2(aga[p], acc1[c][p]);
        }
        __syncthreads();
    }

    // ---- sc = s @ out_w + out_b  (reduce over feature dim) ----
    {
        float ow = out_w[g];
        float pr[TA];
        #pragma unroll
        for (int a = 0; a < TA; a++) pr[a] = hbT[g][a] * ow;
        #pragma unroll
        for (int off = 16; off > 0; off >>= 1) {
            #pragma unroll
            for (int a = 0; a < TA; a++)
                pr[a] += __shfl_xor_sync(0xffffffff, pr[a], off);
        }
        int lane = g & 31, warp = g >> 5;
        if (lane == 0) {
            #pragma unroll
            for (int a = 0; a < TA; a++) red[a][warp] = pr[a];
        }
        __syncthreads();
        if (g < TA)
            scs[g] = red[g][0] + red[g][1] + red[g][2] + red[g][3] + out_b[0];
        __syncthreads();
    }

    // ---- masked segment sum ----
    for (int b = g; b < n_graphs; b += blockDim.x) {
        float acc = 0.0f;
        const float* mrow = mask + (size_t)b * n_atoms + atom0;
        for (int a = 0; a < na; a++)
            acc = fmaf(scs[a], mrow[a], acc);
        atomicAdd(&out[b], acc);
    }
}

extern "C" void kernel_launch(void* const* d_in, const int* in_sizes, int n_in,
                              void* d_out, int out_size) {
    const float* s    = (const float*)d_in[0];
    const float* v    = (const float*)d_in[1];
    // d_in[2] = r (unused)
    const float* mask = (const float*)d_in[3];
    const float* w1   = (const float*)d_in[4];
    const float* w2   = (const float*)d_in[5];
    const float* a1w  = (const float*)d_in[6];
    const float* a1b  = (const float*)d_in[7];
    const float* a2w  = (const float*)d_in[8];
    const float* a2b  = (const float*)d_in[9];
    const float* ow   = (const float*)d_in[10];
    const float* ob   = (const float*)d_in[11];
    float* out = (float*)d_out;

    int n_atoms  = in_sizes[0] / F;
    int n_graphs = out_size;
    int n_layers = in_sizes[7] / F;

    zero_out_kernel<<<(out_size + 127) / 128, 128>>>(out, out_size);

    int grid = (n_atoms + TA - 1) / TA;
    fused_kernel<<<grid, 128>>>(s, v, mask, w1, w2, a1w, a1b, a2w, a2b,
                                ow, ob, out, n_atoms, n_graphs, n_layers);
}

// round 3
// speedup vs baseline: 1.3613x; 1.0019x over previous
#include <cuda_runtime.h>
#include <math.h>

#define F 128
#define TA 8
#define NP 4   // atom pairs

typedef unsigned long long ull;

__device__ __forceinline__ ull dup2(float w) {
    ull r;
    asm("mov.b64 %0, {%1, %1};" : "=l"(r) : "f"(w));
    return r;
}
__device__ __forceinline__ ull pack2(float lo, float hi) {
    ull r;
    asm("mov.b64 %0, {%1, %2};" : "=l"(r) : "f"(lo), "f"(hi));
    return r;
}
__device__ __forceinline__ void unpack2(ull u, float& lo, float& hi) {
    asm("mov.b64 {%0, %1}, %2;" : "=f"(lo), "=f"(hi) : "l"(u));
}
__device__ __forceinline__ void ffma2(ull& a, ull v, ull w) {
    asm("fma.rn.f32x2 %0, %1, %2, %0;" : "+l"(a) : "l"(v), "l"(w));
}
__device__ __forceinline__ ull fmul2(ull v, ull w) {
    ull r;
    asm("mul.rn.f32x2 %0, %1, %2;" : "=l"(r) : "l"(v), "l"(w));
    return r;
}
__device__ __forceinline__ ull fadd2(ull v, ull w) {
    ull r;
    asm("add.rn.f32x2 %0, %1, %2;" : "=l"(r) : "l"(v), "l"(w));
    return r;
}

__global__ void zero_out_kernel(float* out, int n) {
    int i = blockIdx.x * blockDim.x + threadIdx.x;
    if (i < n) out[i] = 0.0f;
}

__global__ void __launch_bounds__(128) fused_kernel(
    const float* __restrict__ s_in, const float* __restrict__ v_in,
    const float* __restrict__ mask,
    const float* __restrict__ w1, const float* __restrict__ w2,
    const float* __restrict__ a1w, const float* __restrict__ a1b,
    const float* __restrict__ a2w, const float* __restrict__ a2b,
    const float* __restrict__ out_w, const float* __restrict__ out_b,
    float* __restrict__ out,
    int n_atoms, int n_graphs, int n_layers)
{
    const int g = threadIdx.x;              // feature index (0..127)
    const int atom0 = blockIdx.x * TA;
    const int na = min(TA, n_atoms - atom0);

    // atom-major tiles: last dim = atom -> packed f32x2 over atom pairs
    __shared__ float svT[3][F][TA];      // 12 KB vector features
    __shared__ float hbT[2 * F][TA];     // 8 KB  concat [s ; n2] / activations
    __shared__ float red[TA][4];
    __shared__ float scs[TA];

    // ---- load tiles (zero-fill inactive atom slots) ----
    #pragma unroll
    for (int a = 0; a < TA; a++) {
        float sval = 0.0f, v0 = 0.0f, v1 = 0.0f, v2 = 0.0f;
        if (a < na) {
            size_t base = (size_t)(atom0 + a);
            sval = s_in[base * F + g];
            v0 = v_in[(base * 3 + 0) * F + g];
            v1 = v_in[(base * 3 + 1) * F + g];
            v2 = v_in[(base * 3 + 2) * F + g];
        }
        hbT[g][a] = sval;
        svT[0][g][a] = v0;
        svT[1][g][a] = v1;
        svT[2][g][a] = v2;
    }
    __syncthreads();

    for (int l = 0; l < n_layers; l++) {
        const float* W1 = w1 + (size_t)l * F * F;
        const float* W2 = w2 + (size_t)l * F * F;
        const float* A1 = a1w + (size_t)l * 2 * F * F;
        const float* A2 = a2w + (size_t)l * F * 2 * F;

        // ---- v1 = v@W1, v2 = v@W2 (thread g = output column g, packed atom pairs) ----
        ull acc1[3][NP], acc2[3][NP];
        #pragma unroll
        for (int c = 0; c < 3; c++)
            #pragma unroll
            for (int p = 0; p < NP; p++) { acc1[c][p] = 0ull; acc2[c][p] = 0ull; }

        #pragma unroll 4
        for (int f = 0; f < F; f++) {
            ull uw1 = dup2(W1[f * F + g]);
            ull uw2 = dup2(W2[f * F + g]);
            #pragma unroll
            for (int c = 0; c < 3; c++) {
                ulonglong2 lo = *(const ulonglong2*)&svT[c][f][0];  // atoms 0-3
                ulonglong2 hi = *(const ulonglong2*)&svT[c][f][4];  // atoms 4-7
                ffma2(acc1[c][0], lo.x, uw1); ffma2(acc2[c][0], lo.x, uw2);
                ffma2(acc1[c][1], lo.y, uw1); ffma2(acc2[c][1], lo.y, uw2);
                ffma2(acc1[c][2], hi.x, uw1); ffma2(acc2[c][2], hi.x, uw2);
                ffma2(acc1[c][3], hi.y, uw1); ffma2(acc2[c][3], hi.y, uw2);
            }
        }

        // ---- n2 = ||v2|| over spatial; h = [s(already in hbT[0:F]), n2] ----
        #pragma unroll
        for (int p = 0; p < NP; p++) {
            ull sq = fmul2(acc2[0][p], acc2[0][p]);
            ffma2(sq, acc2[1][p], acc2[1][p]);
            ffma2(sq, acc2[2][p], acc2[2][p]);
            float q0, q1; unpack2(sq, q0, q1);
            *(ull*)&hbT[F + g][2 * p] = pack2(sqrtf(q0), sqrtf(q1));
        }
        __syncthreads();

        // ---- act = silu(h @ A1 + b1) ----
        ull acc[NP];
        #pragma unroll
        for (int p = 0; p < NP; p++) acc[p] = 0ull;
        #pragma unroll 4
        for (int f = 0; f < 2 * F; f++) {
            ull uw = dup2(A1[f * F + g]);
            ulonglong2 lo = *(const ulonglong2*)&hbT[f][0];
            ulonglong2 hi = *(const ulonglong2*)&hbT[f][4];
            ffma2(acc[0], lo.x, uw);
            ffma2(acc[1], lo.y, uw);
            ffma2(acc[2], hi.x, uw);
            ffma2(acc[3], hi.y, uw);
        }
        {
            float b = a1b[l * F + g];
            #pragma unroll
            for (int p = 0; p < NP; p++) {
                float x0, x1; unpack2(acc[p], x0, x1);
                x0 += b; x1 += b;
                x0 = x0 / (1.0f + expf(-x0));
                x1 = x1 / (1.0f + expf(-x1));
                acc[p] = pack2(x0, x1);
            }
        }
        __syncthreads();                 // all hbT reads done before overwrite
        #pragma unroll
        for (int p = 0; p < NP; p++)
            *(ull*)&hbT[g][2 * p] = acc[p];
        __syncthreads();

        // ---- h2 = act @ A2 + b2 ; first F -> s_out, second F -> gate ----
        ull aso[NP], aga[NP];
        #pragma unroll
        for (int p = 0; p < NP; p++) { aso[p] = 0ull; aga[p] = 0ull; }
        #pragma unroll 4
        for (int f = 0; f < F; f++) {
            ull uwA = dup2(A2[f * 2 * F + g]);
            ull uwB = dup2(A2[f * 2 * F + F + g]);
            ulonglong2 lo = *(const ulonglong2*)&hbT[f][0];
            ulonglong2 hi = *(const ulonglong2*)&hbT[f][4];
            ffma2(aso[0], lo.x, uwA); ffma2(aga[0], lo.x, uwB);
            ffma2(aso[1], lo.y, uwA); ffma2(aga[1], lo.y, uwB);
            ffma2(aso[2], hi.x, uwA); ffma2(aga[2], hi.x, uwB);
            ffma2(aso[3], hi.y, uwA); ffma2(aga[3], hi.y, uwB);
        }
        {
            ull ubA = dup2(a2b[l * 2 * F + g]);
            ull ubB = dup2(a2b[l * 2 * F + F + g]);
            #pragma unroll
            for (int p = 0; p < NP; p++) {
                aso[p] = fadd2(aso[p], ubA);
                aga[p] = fadd2(aga[p], ubB);
            }
        }

        __syncthreads();                 // all hbT/svT reads done before overwrite
        #pragma unroll
        for (int p = 0; p < NP; p++) {
            *(ull*)&hbT[g][2 * p] = aso[p];          // s for next layer
            #pragma unroll
            for (int c = 0; c < 3; c++)
                *(ull*)&svT[c][g][2 * p] = fmul2(aga[p], acc1[c][p]);
        }
        __syncthreads();
    }

    // ---- sc = s @ out_w + out_b  (reduce over feature dim) ----
    {
        float ow = out_w[g];
        float pr[TA];
        #pragma unroll
        for (int a = 0; a < TA; a++) pr[a] = hbT[g][a] * ow;
        #pragma unroll
        for (int off = 16; off > 0; off >>= 1) {
            #pragma unroll
            for (int a = 0; a < TA; a++)
                pr[a] += __shfl_xor_sync(0xffffffff, pr[a], off);
        }
        int lane = g & 31, warp = g >> 5;
        if (lane == 0) {
            #pragma unroll
            for (int a = 0; a < TA; a++) red[a][warp] = pr[a];
        }
        __syncthreads();
        if (g < TA)
            scs[g] = red[g][0] + red[g][1] + red[g][2] + red[g][3] + out_b[0];
        __syncthreads();
    }

    // ---- masked segment sum ----
    for (int b = g; b < n_graphs; b += blockDim.x) {
        float acc = 0.0f;
        const float* mrow = mask + (size_t)b * n_atoms + atom0;
        for (int a = 0; a < na; a++)
            acc = fmaf(scs[a], mrow[a], acc);
        atomicAdd(&out[b], acc);
    }
}

extern "C" void kernel_launch(void* const* d_in, const int* in_sizes, int n_in,
                              void* d_out, int out_size) {
    const float* s    = (const float*)d_in[0];
    const float* v    = (const float*)d_in[1];
    // d_in[2] = r (unused)
    const float* mask = (const float*)d_in[3];
    const float* w1   = (const float*)d_in[4];
    const float* w2   = (const float*)d_in[5];
    const float* a1w  = (const float*)d_in[6];
    const float* a1b  = (const float*)d_in[7];
    const float* a2w  = (const float*)d_in[8];
    const float* a2b  = (const float*)d_in[9];
    const float* ow   = (const float*)d_in[10];
    const float* ob   = (const float*)d_in[11];
    float* out = (float*)d_out;

    int n_atoms  = in_sizes[0] / F;
    int n_graphs = out_size;
    int n_layers = in_sizes[7] / F;

    zero_out_kernel<<<(out_size + 127) / 128, 128>>>(out, out_size);

    int grid = (n_atoms + TA - 1) / TA;
    fused_kernel<<<grid, 128>>>(s, v, mask, w1, w2, a1w, a1b, a2w, a2b,
                                ow, ob, out, n_atoms, n_graphs, n_layers);
}

// round 5
// speedup vs baseline: 1.9185x; 1.4094x over previous
#include <cuda_runtime.h>
#include <cuda_bf16.h>
#include <stdint.h>
#include <math.h>

#define F 128
#define TB 32            // atoms per block
#define THREADS 256
#define LMAX 2

// ---- precomputed weight fragments (uint4 = {bh0,bh1,bl0,bl1}) --------------
__device__ uint4 g_B1[LMAX * 8 * 32 * 32];    // GEMM1: K=128(8 k16), N=256(32 n8)
__device__ uint4 g_B2[LMAX * 16 * 16 * 32];   // GEMM2: K=256, N=128
__device__ uint4 g_B3[LMAX * 8 * 32 * 32];    // GEMM3: K=128, N=256

// ---- helpers ---------------------------------------------------------------
__device__ __forceinline__ uint32_t pack_bf(float x, float y) {
    __nv_bfloat16 hx = __float2bfloat16(x), hy = __float2bfloat16(y);
    uint16_t ux = *(uint16_t*)&hx, uy = *(uint16_t*)&hy;
    return (uint32_t)ux | ((uint32_t)uy << 16);
}
__device__ __forceinline__ void split_pair(float x, float y,
                                           uint32_t& hi, uint32_t& lo) {
    __nv_bfloat16 hx = __float2bfloat16(x), hy = __float2bfloat16(y);
    float fx = __bfloat162float(hx), fy = __bfloat162float(hy);
    uint16_t ux = *(uint16_t*)&hx, uy = *(uint16_t*)&hy;
    hi = (uint32_t)ux | ((uint32_t)uy << 16);
    lo = pack_bf(x - fx, y - fy);
}
__device__ __forceinline__ void mma_bf16(float* d, const uint32_t* a,
                                         uint32_t b0, uint32_t b1) {
    asm volatile(
        "mma.sync.aligned.m16n8k16.row.col.f32.bf16.bf16.f32 "
        "{%0,%1,%2,%3}, {%4,%5,%6,%7}, {%8,%9}, {%0,%1,%2,%3};"
        : "+f"(d[0]), "+f"(d[1]), "+f"(d[2]), "+f"(d[3])
        : "r"(a[0]), "r"(a[1]), "r"(a[2]), "r"(a[3]), "r"(b0), "r"(b1));
}
// load A fragment (16x16) from fp32 smem (row-major, stride floats), split hi/lo
__device__ __forceinline__ void load_afrag(const float* base, int row0, int col0,
                                           int stride, int gq, int tg,
                                           uint32_t* Ah, uint32_t* Al) {
    const float* p = base + (row0 + gq) * stride + col0 + tg * 2;
    float2 v0 = *(const float2*)p;                       // row g,   col c
    float2 v1 = *(const float2*)(p + 8 * stride);        // row g+8, col c
    float2 v2 = *(const float2*)(p + 8);                 // row g,   col c+8
    float2 v3 = *(const float2*)(p + 8 * stride + 8);    // row g+8, col c+8
    split_pair(v0.x, v0.y, Ah[0], Al[0]);
    split_pair(v1.x, v1.y, Ah[1], Al[1]);
    split_pair(v2.x, v2.y, Ah[2], Al[2]);
    split_pair(v3.x, v3.y, Ah[3], Al[3]);
}

// ---- weight prep kernels ---------------------------------------------------
__device__ __forceinline__ uint4 make_bfrag(float k0v, float k1v, float k8v, float k9v) {
    uint4 r;
    uint32_t h0, l0, h1, l1;
    split_pair(k0v, k1v, h0, l0);
    split_pair(k8v, k9v, h1, l1);
    r.x = h0; r.y = h1; r.z = l0; r.w = l1;
    return r;
}
__global__ void prep1(const float* __restrict__ w1, const float* __restrict__ w2, int L) {
    int i = blockIdx.x * blockDim.x + threadIdx.x;
    if (i >= L * 8 * 32 * 32) return;
    int lane = i & 31, n8 = (i >> 5) & 31, k16 = (i >> 10) & 7, l = i >> 13;
    int tg = lane & 3, gq = lane >> 2;
    int n = n8 * 8 + gq, k0 = k16 * 16 + tg * 2;
    const float* W = (n < 128) ? (w1 + (size_t)l * 16384) : (w2 + (size_t)l * 16384);
    int nn = n & 127;
    g_B1[i] = make_bfrag(W[k0 * 128 + nn], W[(k0 + 1) * 128 + nn],
                         W[(k0 + 8) * 128 + nn], W[(k0 + 9) * 128 + nn]);
}
__global__ void prep2(const float* __restrict__ a1w, int L) {
    int i = blockIdx.x * blockDim.x + threadIdx.x;
    if (i >= L * 16 * 16 * 32) return;
    int lane = i & 31, n8 = (i >> 5) & 15, k16 = (i >> 9) & 15, l = i >> 13;
    int tg = lane & 3, gq = lane >> 2;
    int n = n8 * 8 + gq, k0 = k16 * 16 + tg * 2;
    const float* W = a1w + (size_t)l * 32768;
    g_B2[i] = make_bfrag(W[k0 * 128 + n], W[(k0 + 1) * 128 + n],
                         W[(k0 + 8) * 128 + n], W[(k0 + 9) * 128 + n]);
}
__global__ void prep3(const float* __restrict__ a2w, int L) {
    int i = blockIdx.x * blockDim.x + threadIdx.x;
    if (i >= L * 8 * 32 * 32) return;
    int lane = i & 31, n8 = (i >> 5) & 31, k16 = (i >> 10) & 7, l = i >> 13;
    int tg = lane & 3, gq = lane >> 2;
    int n = n8 * 8 + gq, k0 = k16 * 16 + tg * 2;
    const float* W = a2w + (size_t)l * 32768;
    g_B3[i] = make_bfrag(W[k0 * 256 + n], W[(k0 + 1) * 256 + n],
                         W[(k0 + 8) * 256 + n], W[(k0 + 9) * 256 + n]);
}

__global__ void zero_out_kernel(float* out, int n) {
    int i = blockIdx.x * blockDim.x + threadIdx.x;
    if (i < n) out[i] = 0.0f;
}

// ---- smem layout (floats) --------------------------------------------------
#define SVP 132                  // padded row stride (96 rows)
#define HBP 260                  // padded row stride (32 rows)
#define OFF_SV  0
#define OFF_V1  (OFF_SV + 96 * SVP)
#define OFF_HB  (OFF_V1 + 96 * SVP)
#define OFF_ACT (OFF_HB + 32 * HBP)
#define OFF_SCS (OFF_ACT + 32 * SVP)
#define SM_FLOATS (OFF_SCS + 32)
#define SM_BYTES  (SM_FLOATS * 4)

// ---- fused kernel ----------------------------------------------------------
__global__ void __launch_bounds__(THREADS) fused_kernel(
    const float* __restrict__ s_in, const float* __restrict__ v_in,
    const float* __restrict__ mask,
    const float* __restrict__ a1b, const float* __restrict__ a2b,
    const float* __restrict__ out_w, const float* __restrict__ out_b,
    float* __restrict__ out,
    int n_atoms, int n_graphs, int n_layers)
{
    extern __shared__ float smf[];
    const int t = threadIdx.x;
    const int wid = t >> 5, lane = t & 31;
    const int tg = lane & 3, gq = lane >> 2;
    const int ag = wid >> 2, ng = wid & 3;
    const int atom0 = blockIdx.x * TB;
    const int na = min(TB, n_atoms - atom0);

    float* SV  = smf + OFF_SV;
    float* V1  = smf + OFF_V1;
    float* HB  = smf + OFF_HB;
    float* ACT = smf + OFF_ACT;
    float* SCS = smf + OFF_SCS;

    // ---- load tiles ----
    for (int i = t; i < 96 * 128; i += THREADS) {
        int r = i >> 7, col = i & 127;
        int c = r >> 5, a = r & 31;
        float val = (a < na) ? v_in[(((size_t)(atom0 + a)) * 3 + c) * F + col] : 0.0f;
        SV[r * SVP + col] = val;
    }
    for (int i = t; i < 32 * 128; i += THREADS) {
        int a = i >> 7, col = i & 127;
        HB[a * HBP + col] = (a < na) ? s_in[(size_t)(atom0 + a) * F + col] : 0.0f;
    }
    __syncthreads();

    for (int l = 0; l < n_layers; l++) {
        // ================= GEMM1: [96x128] @ [128x256] = [v1 | v2] ==========
        {
            const uint4* B1 = g_B1 + (size_t)l * 8 * 32 * 32;
            float sq[8][4];
            #pragma unroll
            for (int n8 = 0; n8 < 8; n8++)
                #pragma unroll
                for (int j = 0; j < 4; j++) sq[n8][j] = 0.0f;

            #pragma unroll
            for (int c = 0; c < 3; c++) {
                float acc[8][4];
                #pragma unroll
                for (int n8 = 0; n8 < 8; n8++)
                    #pragma unroll
                    for (int j = 0; j < 4; j++) acc[n8][j] = 0.0f;
                const int arow = c * 32 + ag * 16;
                #pragma unroll
                for (int k16 = 0; k16 < 8; k16++) {
                    uint32_t Ah[4], Al[4];
                    load_afrag(SV, arow, k16 * 16, SVP, gq, tg, Ah, Al);
                    #pragma unroll
                    for (int n8 = 0; n8 < 8; n8++) {
                        uint4 bb = B1[(k16 * 32 + ng * 8 + n8) * 32 + lane];
                        mma_bf16(acc[n8], Ah, bb.x, bb.y);
                        mma_bf16(acc[n8], Ah, bb.z, bb.w);
                        mma_bf16(acc[n8], Al, bb.x, bb.y);
                    }
                }
                if (ng < 2) {   // v1 columns -> smem
                    #pragma unroll
                    for (int n8 = 0; n8 < 8; n8++)
                        #pragma unroll
                        for (int j = 0; j < 4; j++) {
                            int row = arow + gq + ((j >> 1) << 3);
                            int col = ng * 64 + n8 * 8 + tg * 2 + (j & 1);
                            V1[row * SVP + col] = acc[n8][j];
                        }
                } else {        // v2 columns -> accumulate squares over c
                    #pragma unroll
                    for (int n8 = 0; n8 < 8; n8++)
                        #pragma unroll
                        for (int j = 0; j < 4; j++)
                            sq[n8][j] += acc[n8][j] * acc[n8][j];
                }
            }
            if (ng >= 2) {      // write n2 into HB[:,128:256]
                #pragma unroll
                for (int n8 = 0; n8 < 8; n8++)
                    #pragma unroll
                    for (int j = 0; j < 4; j++) {
                        int a = ag * 16 + gq + ((j >> 1) << 3);
                        int gcol = (ng - 2) * 64 + n8 * 8 + tg * 2 + (j & 1);
                        HB[a * HBP + 128 + gcol] = sqrtf(sq[n8][j]);
                    }
            }
        }
        __syncthreads();

        // ================= GEMM2: [32x256] @ [256x128] -> silu -> ACT =======
        {
            const uint4* B2 = g_B2 + (size_t)l * 16 * 16 * 32;
            float acc[4][4];
            #pragma unroll
            for (int n8 = 0; n8 < 4; n8++)
                #pragma unroll
                for (int j = 0; j < 4; j++) acc[n8][j] = 0.0f;
            const int arow = ag * 16;
            #pragma unroll
            for (int k16 = 0; k16 < 16; k16++) {
                uint32_t Ah[4], Al[4];
                load_afrag(HB, arow, k16 * 16, HBP, gq, tg, Ah, Al);
                #pragma unroll
                for (int n8 = 0; n8 < 4; n8++) {
                    uint4 bb = B2[(k16 * 16 + ng * 4 + n8) * 32 + lane];
                    mma_bf16(acc[n8], Ah, bb.x, bb.y);
                    mma_bf16(acc[n8], Ah, bb.z, bb.w);
                    mma_bf16(acc[n8], Al, bb.x, bb.y);
                }
            }
            #pragma unroll
            for (int n8 = 0; n8 < 4; n8++)
                #pragma unroll
                for (int j = 0; j < 4; j++) {
                    int a = arow + gq + ((j >> 1) << 3);
                    int col = ng * 32 + n8 * 8 + tg * 2 + (j & 1);
                    float x = acc[n8][j] + a1b[l * F + col];
                    ACT[a * SVP + col] = x / (1.0f + expf(-x));
                }
        }
        __syncthreads();

        // ================= GEMM3: [32x128] @ [128x256] -> s_out | gate ======
        {
            const uint4* B3 = g_B3 + (size_t)l * 8 * 32 * 32;
            float acc[8][4];
            #pragma unroll
            for (int n8 = 0; n8 < 8; n8++)
                #pragma unroll
                for (int j = 0; j < 4; j++) acc[n8][j] = 0.0f;
            const int arow = ag * 16;
            #pragma unroll
            for (int k16 = 0; k16 < 8; k16++) {
                uint32_t Ah[4], Al[4];
                load_afrag(ACT, arow, k16 * 16, SVP, gq, tg, Ah, Al);
                #pragma unroll
                for (int n8 = 0; n8 < 8; n8++) {
                    uint4 bb = B3[(k16 * 32 + ng * 8 + n8) * 32 + lane];
                    mma_bf16(acc[n8], Ah, bb.x, bb.y);
                    mma_bf16(acc[n8], Ah, bb.z, bb.w);
                    mma_bf16(acc[n8], Al, bb.x, bb.y);
                }
            }
            // epilogue: cols<128 -> new s; cols>=128 -> gate * v1 -> SV
            #pragma unroll
            for (int n8 = 0; n8 < 8; n8++)
                #pragma unroll
                for (int j = 0; j < 4; j++) {
                    int a = arow + gq + ((j >> 1) << 3);
                    int col = ng * 64 + n8 * 8 + tg * 2 + (j & 1);
                    float x = acc[n8][j] + a2b[l * 256 + col];
                    if (col < 128) {
                        HB[a * HBP + col] = x;
                    } else {
                        int gcol = col - 128;
                        #pragma unroll
                        for (int c = 0; c < 3; c++) {
                            int row = c * 32 + a;
                            SV[row * SVP + gcol] = x * V1[row * SVP + gcol];
                        }
                    }
                }
        }
        __syncthreads();
    }

    // ---- sc[a] = dot(s[a], out_w) + ob ----
    {
        float ow0 = out_w[lane], ow1 = out_w[lane + 32];
        float ow2 = out_w[lane + 64], ow3 = out_w[lane + 96];
        #pragma unroll
        for (int ai = 0; ai < 4; ai++) {
            int a = wid * 4 + ai;
            const float* row = HB + a * HBP;
            float acc = row[lane] * ow0 + row[lane + 32] * ow1 +
                        row[lane + 64] * ow2 + row[lane + 96] * ow3;
            #pragma unroll
            for (int off = 16; off > 0; off >>= 1)
                acc += __shfl_xor_sync(0xffffffff, acc, off);
            if (lane == 0) SCS[a] = acc + out_b[0];
        }
    }
    __syncthreads();

    // ---- masked segment sum ----
    for (int b = t; b < n_graphs; b += THREADS) {
        float acc = 0.0f;
        const float* mrow = mask + (size_t)b * n_atoms + atom0;
        for (int a = 0; a < na; a++)
            acc = fmaf(SCS[a], mrow[a], acc);
        atomicAdd(&out[b], acc);
    }
}

// ---- host ------------------------------------------------------------------
extern "C" void kernel_launch(void* const* d_in, const int* in_sizes, int n_in,
                              void* d_out, int out_size) {
    const float* s    = (const float*)d_in[0];
    const float* v    = (const float*)d_in[1];
    const float* mask = (const float*)d_in[3];
    const float* w1   = (const float*)d_in[4];
    const float* w2   = (const float*)d_in[5];
    const float* a1w  = (const float*)d_in[6];
    const float* a1b  = (const float*)d_in[7];
    const float* a2w  = (const float*)d_in[8];
    const float* a2b  = (const float*)d_in[9];
    const float* ow   = (const float*)d_in[10];
    const float* ob   = (const float*)d_in[11];
    float* out = (float*)d_out;

    const int NA = in_sizes[0] / F;
    const int L  = in_sizes[7] / F;
    const int NG = out_size;

    cudaFuncSetAttribute(fused_kernel, cudaFuncAttributeMaxDynamicSharedMemorySize,
                         SM_BYTES);

    prep1<<<(L * 8192 + 255) / 256, 256>>>(w1, w2, L);
    prep2<<<(L * 8192 + 255) / 256, 256>>>(a1w, L);
    prep3<<<(L * 8192 + 255) / 256, 256>>>(a2w, L);
    zero_out_kernel<<<(out_size + 127) / 128, 128>>>(out, out_size);

    int grid = (NA + TB - 1) / TB;
    fused_kernel<<<grid, THREADS, SM_BYTES>>>(s, v, mask, a1b, a2b, ow, ob, out,
                                              NA, NG, L);
}

// round 6
// speedup vs baseline: 2.2401x; 1.1676x over previous
#include <cuda_runtime.h>
#include <cuda_bf16.h>
#include <stdint.h>
#include <math.h>

#define F 128
#define TB 32            // atoms per block
#define THREADS 256
#define LMAX 2

// ---- precomputed weight fragments (uint4 = {bh0,bh1,bl0,bl1}) --------------
__device__ uint4 g_B1[LMAX * 8 * 32 * 32];    // GEMM1: K=128(8 k16), N=256(32 n8)
__device__ uint4 g_B2[LMAX * 16 * 16 * 32];   // GEMM2: K=256, N=128
__device__ uint4 g_B3[LMAX * 8 * 32 * 32];    // GEMM3: K=128, N=256

// ---- helpers ---------------------------------------------------------------
__device__ __forceinline__ uint32_t pack_bf(float x, float y) {
    __nv_bfloat16 hx = __float2bfloat16(x), hy = __float2bfloat16(y);
    uint16_t ux = *(uint16_t*)&hx, uy = *(uint16_t*)&hy;
    return (uint32_t)ux | ((uint32_t)uy << 16);
}
__device__ __forceinline__ void split_pair(float x, float y,
                                           uint32_t& hi, uint32_t& lo) {
    __nv_bfloat16 hx = __float2bfloat16(x), hy = __float2bfloat16(y);
    float fx = __bfloat162float(hx), fy = __bfloat162float(hy);
    uint16_t ux = *(uint16_t*)&hx, uy = *(uint16_t*)&hy;
    hi = (uint32_t)ux | ((uint32_t)uy << 16);
    lo = pack_bf(x - fx, y - fy);
}
__device__ __forceinline__ void mma_bf16(float* d, const uint32_t* a,
                                         uint32_t b0, uint32_t b1) {
    asm volatile(
        "mma.sync.aligned.m16n8k16.row.col.f32.bf16.bf16.f32 "
        "{%0,%1,%2,%3}, {%4,%5,%6,%7}, {%8,%9}, {%0,%1,%2,%3};"
        : "+f"(d[0]), "+f"(d[1]), "+f"(d[2]), "+f"(d[3])
        : "r"(a[0]), "r"(a[1]), "r"(a[2]), "r"(a[3]), "r"(b0), "r"(b1));
}
__device__ __forceinline__ void ldm_x4(uint32_t* r, uint32_t addr) {
    asm volatile("ldmatrix.sync.aligned.m8n8.x4.shared.b16 {%0,%1,%2,%3}, [%4];"
        : "=r"(r[0]), "=r"(r[1]), "=r"(r[2]), "=r"(r[3]) : "r"(addr));
}
__device__ __forceinline__ uint32_t smem_u32(const void* p) {
    uint32_t a;
    asm("{ .reg .u64 t; cvta.to.shared.u64 t, %1; cvt.u32.u64 %0, t; }"
        : "=r"(a) : "l"(p));
    return a;
}

// ---- weight prep kernels ---------------------------------------------------
__device__ __forceinline__ uint4 make_bfrag(float k0v, float k1v, float k8v, float k9v) {
    uint4 r;
    uint32_t h0, l0, h1, l1;
    split_pair(k0v, k1v, h0, l0);
    split_pair(k8v, k9v, h1, l1);
    r.x = h0; r.y = h1; r.z = l0; r.w = l1;
    return r;
}
__global__ void prep1(const float* __restrict__ w1, const float* __restrict__ w2, int L) {
    int i = blockIdx.x * blockDim.x + threadIdx.x;
    if (i >= L * 8 * 32 * 32) return;
    int lane = i & 31, n8 = (i >> 5) & 31, k16 = (i >> 10) & 7, l = i >> 13;
    int tg = lane & 3, gq = lane >> 2;
    int n = n8 * 8 + gq, k0 = k16 * 16 + tg * 2;
    const float* W = (n < 128) ? (w1 + (size_t)l * 16384) : (w2 + (size_t)l * 16384);
    int nn = n & 127;
    g_B1[i] = make_bfrag(W[k0 * 128 + nn], W[(k0 + 1) * 128 + nn],
                         W[(k0 + 8) * 128 + nn], W[(k0 + 9) * 128 + nn]);
}
__global__ void prep2(const float* __restrict__ a1w, int L) {
    int i = blockIdx.x * blockDim.x + threadIdx.x;
    if (i >= L * 16 * 16 * 32) return;
    int lane = i & 31, n8 = (i >> 5) & 15, k16 = (i >> 9) & 15, l = i >> 13;
    int tg = lane & 3, gq = lane >> 2;
    int n = n8 * 8 + gq, k0 = k16 * 16 + tg * 2;
    const float* W = a1w + (size_t)l * 32768;
    g_B2[i] = make_bfrag(W[k0 * 128 + n], W[(k0 + 1) * 128 + n],
                         W[(k0 + 8) * 128 + n], W[(k0 + 9) * 128 + n]);
}
__global__ void prep3(const float* __restrict__ a2w, int L) {
    int i = blockIdx.x * blockDim.x + threadIdx.x;
    if (i >= L * 8 * 32 * 32) return;
    int lane = i & 31, n8 = (i >> 5) & 31, k16 = (i >> 10) & 7, l = i >> 13;
    int tg = lane & 3, gq = lane >> 2;
    int n = n8 * 8 + gq, k0 = k16 * 16 + tg * 2;
    const float* W = a2w + (size_t)l * 32768;
    g_B3[i] = make_bfrag(W[k0 * 256 + n], W[(k0 + 1) * 256 + n],
                         W[(k0 + 8) * 256 + n], W[(k0 + 9) * 256 + n]);
}

__global__ void zero_out_kernel(float* out, int n) {
    int i = blockIdx.x * blockDim.x + threadIdx.x;
    if (i < n) out[i] = 0.0f;
}

// ---- smem layout (bytes) ----------------------------------------------------
// bf16 planes: strides chosen so stride_words % 32 == 4 (conflict-free ldmatrix)
#define SV_S 136                 // [96][128] bf16, stride 136 elems (272B)
#define HB_S 264                 // [32][256] bf16, stride 264 elems (528B)
#define AC_S 136                 // [32][128] bf16
#define V1_S 132                 // [96][132] fp32
#define OFF_SVH  0
#define OFF_SVL  (OFF_SVH + 96 * SV_S * 2)       // 26112
#define OFF_HBH  (OFF_SVL + 96 * SV_S * 2)       // 52224
#define OFF_HBL  (OFF_HBH + 32 * HB_S * 2)       // 69120
#define OFF_ACH  (OFF_HBL + 32 * HB_S * 2)       // 86016
#define OFF_ACL  (OFF_ACH + 32 * AC_S * 2)       // 94720
#define OFF_V1   (OFF_ACL + 32 * AC_S * 2)       // 103424
#define OFF_SCS  (OFF_V1 + 96 * V1_S * 4)        // 154112
#define SM_BYTES (OFF_SCS + 32 * 4)              // 154240

__device__ __forceinline__ uint32_t ldm_addr(uint32_t plane, int row0, int stride,
                                             int lane) {
    return plane + (uint32_t)(((row0 + (lane & 15)) * stride +
                               ((lane >> 4) << 3)) * 2);
}
__device__ __forceinline__ void split_store(char* sm, int offH, int offL,
                                            int row, int stride, int col,
                                            float x0, float x1) {
    uint32_t h, l;
    split_pair(x0, x1, h, l);
    *(uint32_t*)(sm + offH + (row * stride + col) * 2) = h;
    *(uint32_t*)(sm + offL + (row * stride + col) * 2) = l;
}

// ---- fused kernel ----------------------------------------------------------
__global__ void __launch_bounds__(THREADS) fused_kernel(
    const float* __restrict__ s_in, const float* __restrict__ v_in,
    const float* __restrict__ mask,
    const float* __restrict__ a1b, const float* __restrict__ a2b,
    const float* __restrict__ out_w, const float* __restrict__ out_b,
    float* __restrict__ out,
    int n_atoms, int n_graphs, int n_layers)
{
    extern __shared__ char sm[];
    const int t = threadIdx.x;
    const int wid = t >> 5, lane = t & 31;
    const int tg = lane & 3, gq = lane >> 2;
    const int ag = wid >> 2, ng = wid & 3;
    const int atom0 = blockIdx.x * TB;
    const int na = min(TB, n_atoms - atom0);
    const uint32_t smb = smem_u32(sm);

    float* V1  = (float*)(sm + OFF_V1);
    float* SCS = (float*)(sm + OFF_SCS);

    // ---- load + split input tiles (pairs of columns) ----
    for (int i = t; i < 96 * 64; i += THREADS) {
        int r = i >> 6, cp = i & 63;           // r = c*32 + a, col pair 2cp
        int c = r >> 5, a = r & 31;
        float2 v = make_float2(0.f, 0.f);
        if (a < na)
            v = *(const float2*)(v_in + (((size_t)(atom0 + a)) * 3 + c) * F + 2 * cp);
        split_store(sm, OFF_SVH, OFF_SVL, r, SV_S, 2 * cp, v.x, v.y);
    }
    for (int i = t; i < 32 * 64; i += THREADS) {
        int a = i >> 6, cp = i & 63;
        float2 v = make_float2(0.f, 0.f);
        if (a < na)
            v = *(const float2*)(s_in + (size_t)(atom0 + a) * F + 2 * cp);
        split_store(sm, OFF_HBH, OFF_HBL, a, HB_S, 2 * cp, v.x, v.y);
    }
    __syncthreads();

    for (int l = 0; l < n_layers; l++) {
        // ================= GEMM1: [96x128] @ [128x256] = [v1 | v2] ==========
        {
            const uint4* B1 = g_B1 + (size_t)l * 8 * 32 * 32;
            float sq[8][4];
            #pragma unroll
            for (int n8 = 0; n8 < 8; n8++)
                #pragma unroll
                for (int j = 0; j < 4; j++) sq[n8][j] = 0.0f;

            #pragma unroll
            for (int c = 0; c < 3; c++) {
                float acc[8][4];
                #pragma unroll
                for (int n8 = 0; n8 < 8; n8++)
                    #pragma unroll
                    for (int j = 0; j < 4; j++) acc[n8][j] = 0.0f;
                const int arow = c * 32 + ag * 16;
                const uint32_t ah = ldm_addr(smb + OFF_SVH, arow, SV_S, lane);
                const uint32_t al = ldm_addr(smb + OFF_SVL, arow, SV_S, lane);
                #pragma unroll
                for (int k16 = 0; k16 < 8; k16++) {
                    uint32_t Ah[4], Al[4];
                    ldm_x4(Ah, ah + k16 * 32);
                    ldm_x4(Al, al + k16 * 32);
                    #pragma unroll
                    for (int n8 = 0; n8 < 8; n8++) {
                        uint4 bb = B1[(k16 * 32 + ng * 8 + n8) * 32 + lane];
                        mma_bf16(acc[n8], Ah, bb.x, bb.y);
                        mma_bf16(acc[n8], Ah, bb.z, bb.w);
                        mma_bf16(acc[n8], Al, bb.x, bb.y);
                    }
                }
                if (ng < 2) {   // v1 columns -> fp32 smem
                    #pragma unroll
                    for (int n8 = 0; n8 < 8; n8++)
                        #pragma unroll
                        for (int j = 0; j < 4; j++) {
                            int row = arow + gq + ((j >> 1) << 3);
                            int col = ng * 64 + n8 * 8 + tg * 2 + (j & 1);
                            V1[row * V1_S + col] = acc[n8][j];
                        }
                } else {        // v2 columns -> accumulate squares over c
                    #pragma unroll
                    for (int n8 = 0; n8 < 8; n8++)
                        #pragma unroll
                        for (int j = 0; j < 4; j++)
                            sq[n8][j] += acc[n8][j] * acc[n8][j];
                }
            }
            if (ng >= 2) {      // write n2 (split) into HB[:,128:256]
                #pragma unroll
                for (int n8 = 0; n8 < 8; n8++)
                    #pragma unroll
                    for (int j = 0; j < 4; j += 2) {
                        int a = ag * 16 + gq + ((j >> 1) << 3);
                        int gcol = (ng - 2) * 64 + n8 * 8 + tg * 2;
                        split_store(sm, OFF_HBH, OFF_HBL, a, HB_S, 128 + gcol,
                                    sqrtf(sq[n8][j]), sqrtf(sq[n8][j + 1]));
                    }
            }
        }
        __syncthreads();

        // ================= GEMM2: [32x256] @ [256x128] -> silu -> ACT =======
        {
            const uint4* B2 = g_B2 + (size_t)l * 16 * 16 * 32;
            float acc[4][4];
            #pragma unroll
            for (int n8 = 0; n8 < 4; n8++)
                #pragma unroll
                for (int j = 0; j < 4; j++) acc[n8][j] = 0.0f;
            const int arow = ag * 16;
            const uint32_t ah = ldm_addr(smb + OFF_HBH, arow, HB_S, lane);
            const uint32_t al = ldm_addr(smb + OFF_HBL, arow, HB_S, lane);
            #pragma unroll
            for (int k16 = 0; k16 < 16; k16++) {
                uint32_t Ah[4], Al[4];
                ldm_x4(Ah, ah + k16 * 32);
                ldm_x4(Al, al + k16 * 32);
                #pragma unroll
                for (int n8 = 0; n8 < 4; n8++) {
                    uint4 bb = B2[(k16 * 16 + ng * 4 + n8) * 32 + lane];
                    mma_bf16(acc[n8], Ah, bb.x, bb.y);
                    mma_bf16(acc[n8], Ah, bb.z, bb.w);
                    mma_bf16(acc[n8], Al, bb.x, bb.y);
                }
            }
            #pragma unroll
            for (int n8 = 0; n8 < 4; n8++)
                #pragma unroll
                for (int j = 0; j < 4; j += 2) {
                    int a = arow + gq + ((j >> 1) << 3);
                    int col = ng * 32 + n8 * 8 + tg * 2;
                    float x0 = acc[n8][j]     + a1b[l * F + col];
                    float x1 = acc[n8][j + 1] + a1b[l * F + col + 1];
                    x0 = x0 / (1.0f + expf(-x0));
                    x1 = x1 / (1.0f + expf(-x1));
                    split_store(sm, OFF_ACH, OFF_ACL, a, AC_S, col, x0, x1);
                }
        }
        __syncthreads();

        // ================= GEMM3: [32x128] @ [128x256] -> s_out | gate ======
        {
            const uint4* B3 = g_B3 + (size_t)l * 8 * 32 * 32;
            float acc[8][4];
            #pragma unroll
            for (int n8 = 0; n8 < 8; n8++)
                #pragma unroll
                for (int j = 0; j < 4; j++) acc[n8][j] = 0.0f;
            const int arow = ag * 16;
            const uint32_t ah = ldm_addr(smb + OFF_ACH, arow, AC_S, lane);
            const uint32_t al = ldm_addr(smb + OFF_ACL, arow, AC_S, lane);
            #pragma unroll
            for (int k16 = 0; k16 < 8; k16++) {
                uint32_t Ah[4], Al[4];
                ldm_x4(Ah, ah + k16 * 32);
                ldm_x4(Al, al + k16 * 32);
                #pragma unroll
                for (int n8 = 0; n8 < 8; n8++) {
                    uint4 bb = B3[(k16 * 32 + ng * 8 + n8) * 32 + lane];
                    mma_bf16(acc[n8], Ah, bb.x, bb.y);
                    mma_bf16(acc[n8], Ah, bb.z, bb.w);
                    mma_bf16(acc[n8], Al, bb.x, bb.y);
                }
            }
            // epilogue: cols<128 -> new s (split); cols>=128 -> gate * V1 -> SV
            #pragma unroll
            for (int n8 = 0; n8 < 8; n8++)
                #pragma unroll
                for (int j = 0; j < 4; j += 2) {
                    int a = arow + gq + ((j >> 1) << 3);
                    int col = ng * 64 + n8 * 8 + tg * 2;
                    float x0 = acc[n8][j]     + a2b[l * 256 + col];
                    float x1 = acc[n8][j + 1] + a2b[l * 256 + col + 1];
                    if (col < 128) {
                        split_store(sm, OFF_HBH, OFF_HBL, a, HB_S, col, x0, x1);
                    } else {
                        int gcol = col - 128;
                        #pragma unroll
                        for (int c = 0; c < 3; c++) {
                            int row = c * 32 + a;
                            float p0 = x0 * V1[row * V1_S + gcol];
                            float p1 = x1 * V1[row * V1_S + gcol + 1];
                            split_store(sm, OFF_SVH, OFF_SVL, row, SV_S, gcol, p0, p1);
                        }
                    }
                }
        }
        __syncthreads();
    }

    // ---- sc[a] = dot(s[a], out_w) + ob ----
    {
        const uint16_t* HH = (const uint16_t*)(sm + OFF_HBH);
        const uint16_t* HL = (const uint16_t*)(sm + OFF_HBL);
        float ow0 = out_w[lane], ow1 = out_w[lane + 32];
        float ow2 = out_w[lane + 64], ow3 = out_w[lane + 96];
        #pragma unroll
        for (int ai = 0; ai < 4; ai++) {
            int a = wid * 4 + ai;
            const uint16_t* rh = HH + a * HB_S;
            const uint16_t* rl = HL + a * HB_S;
            float s0 = __bfloat162float(*(__nv_bfloat16*)&rh[lane]) +
                       __bfloat162float(*(__nv_bfloat16*)&rl[lane]);
            float s1 = __bfloat162float(*(__nv_bfloat16*)&rh[lane + 32]) +
                       __bfloat162float(*(__nv_bfloat16*)&rl[lane + 32]);
            float s2 = __bfloat162float(*(__nv_bfloat16*)&rh[lane + 64]) +
                       __bfloat162float(*(__nv_bfloat16*)&rl[lane + 64]);
            float s3 = __bfloat162float(*(__nv_bfloat16*)&rh[lane + 96]) +
                       __bfloat162float(*(__nv_bfloat16*)&rl[lane + 96]);
            float acc = s0 * ow0 + s1 * ow1 + s2 * ow2 + s3 * ow3;
            #pragma unroll
            for (int off = 16; off > 0; off >>= 1)
                acc += __shfl_xor_sync(0xffffffff, acc, off);
            if (lane == 0) SCS[a] = acc + out_b[0];
        }
    }
    __syncthreads();

    // ---- masked segment sum ----
    for (int b = t; b < n_graphs; b += THREADS) {
        float acc = 0.0f;
        const float* mrow = mask + (size_t)b * n_atoms + atom0;
        for (int a = 0; a < na; a++)
            acc = fmaf(SCS[a], mrow[a], acc);
        atomicAdd(&out[b], acc);
    }
}

// ---- host ------------------------------------------------------------------
extern "C" void kernel_launch(void* const* d_in, const int* in_sizes, int n_in,
                              void* d_out, int out_size) {
    const float* s    = (const float*)d_in[0];
    const float* v    = (const float*)d_in[1];
    const float* mask = (const float*)d_in[3];
    const float* w1   = (const float*)d_in[4];
    const float* w2   = (const float*)d_in[5];
    const float* a1w  = (const float*)d_in[6];
    const float* a1b  = (const float*)d_in[7];
    const float* a2w  = (const float*)d_in[8];
    const float* a2b  = (const float*)d_in[9];
    const float* ow   = (const float*)d_in[10];
    const float* ob   = (const float*)d_in[11];
    float* out = (float*)d_out;

    const int NA = in_sizes[0] / F;
    const int L  = in_sizes[7] / F;
    const int NG = out_size;

    cudaFuncSetAttribute(fused_kernel, cudaFuncAttributeMaxDynamicSharedMemorySize,
                         SM_BYTES);

    prep1<<<(L * 8192 + 255) / 256, 256>>>(w1, w2, L);
    prep2<<<(L * 8192 + 255) / 256, 256>>>(a1w, L);
    prep3<<<(L * 8192 + 255) / 256, 256>>>(a2w, L);
    zero_out_kernel<<<(out_size + 127) / 128, 128>>>(out, out_size);

    int grid = (NA + TB - 1) / TB;
    fused_kernel<<<grid, THREADS, SM_BYTES>>>(s, v, mask, a1b, a2b, ow, ob, out,
                                              NA, NG, L);
}

// round 7
// speedup vs baseline: 2.9812x; 1.3309x over previous
#include <cuda_runtime.h>
#include <cuda_bf16.h>
#include <stdint.h>
#include <math.h>

#define F 128
#define TB 32            // atoms per block
#define THREADS 512
#define LMAX 2

// ---- precomputed weight fragments (uint4 = {bh0,bh1,bl0,bl1}) --------------
__device__ uint4 g_B1[LMAX * 8 * 32 * 32];    // GEMM1: K=128(8 k16), N=256(32 n8)
__device__ uint4 g_B2[LMAX * 16 * 16 * 32];   // GEMM2: K=256, N=128
__device__ uint4 g_B3[LMAX * 8 * 32 * 32];    // GEMM3: K=128, N=256

// ---- helpers ---------------------------------------------------------------
__device__ __forceinline__ uint32_t pack_bf(float x, float y) {
    __nv_bfloat16 hx = __float2bfloat16(x), hy = __float2bfloat16(y);
    uint16_t ux = *(uint16_t*)&hx, uy = *(uint16_t*)&hy;
    return (uint32_t)ux | ((uint32_t)uy << 16);
}
__device__ __forceinline__ void split_pair(float x, float y,
                                           uint32_t& hi, uint32_t& lo) {
    __nv_bfloat16 hx = __float2bfloat16(x), hy = __float2bfloat16(y);
    float fx = __bfloat162float(hx), fy = __bfloat162float(hy);
    uint16_t ux = *(uint16_t*)&hx, uy = *(uint16_t*)&hy;
    hi = (uint32_t)ux | ((uint32_t)uy << 16);
    lo = pack_bf(x - fx, y - fy);
}
__device__ __forceinline__ void mma_bf16(float* d, const uint32_t* a,
                                         uint32_t b0, uint32_t b1) {
    asm volatile(
        "mma.sync.aligned.m16n8k16.row.col.f32.bf16.bf16.f32 "
        "{%0,%1,%2,%3}, {%4,%5,%6,%7}, {%8,%9}, {%0,%1,%2,%3};"
        : "+f"(d[0]), "+f"(d[1]), "+f"(d[2]), "+f"(d[3])
        : "r"(a[0]), "r"(a[1]), "r"(a[2]), "r"(a[3]), "r"(b0), "r"(b1));
}
__device__ __forceinline__ void ldm_x4(uint32_t* r, uint32_t addr) {
    asm volatile("ldmatrix.sync.aligned.m8n8.x4.shared.b16 {%0,%1,%2,%3}, [%4];"
        : "=r"(r[0]), "=r"(r[1]), "=r"(r[2]), "=r"(r[3]) : "r"(addr));
}
__device__ __forceinline__ uint32_t smem_u32(const void* p) {
    uint32_t a;
    asm("{ .reg .u64 t; cvta.to.shared.u64 t, %1; cvt.u32.u64 %0, t; }"
        : "=r"(a) : "l"(p));
    return a;
}

// ---- weight prep kernels ---------------------------------------------------
__device__ __forceinline__ uint4 make_bfrag(float k0v, float k1v, float k8v, float k9v) {
    uint4 r;
    uint32_t h0, l0, h1, l1;
    split_pair(k0v, k1v, h0, l0);
    split_pair(k8v, k9v, h1, l1);
    r.x = h0; r.y = h1; r.z = l0; r.w = l1;
    return r;
}
__global__ void prep1(const float* __restrict__ w1, const float* __restrict__ w2, int L) {
    int i = blockIdx.x * blockDim.x + threadIdx.x;
    if (i >= L * 8 * 32 * 32) return;
    int lane = i & 31, n8 = (i >> 5) & 31, k16 = (i >> 10) & 7, l = i >> 13;
    int tg = lane & 3, gq = lane >> 2;
    int n = n8 * 8 + gq, k0 = k16 * 16 + tg * 2;
    const float* W = (n < 128) ? (w1 + (size_t)l * 16384) : (w2 + (size_t)l * 16384);
    int nn = n & 127;
    g_B1[i] = make_bfrag(W[k0 * 128 + nn], W[(k0 + 1) * 128 + nn],
                         W[(k0 + 8) * 128 + nn], W[(k0 + 9) * 128 + nn]);
}
__global__ void prep2(const float* __restrict__ a1w, int L) {
    int i = blockIdx.x * blockDim.x + threadIdx.x;
    if (i >= L * 16 * 16 * 32) return;
    int lane = i & 31, n8 = (i >> 5) & 15, k16 = (i >> 9) & 15, l = i >> 13;
    int tg = lane & 3, gq = lane >> 2;
    int n = n8 * 8 + gq, k0 = k16 * 16 + tg * 2;
    const float* W = a1w + (size_t)l * 32768;
    g_B2[i] = make_bfrag(W[k0 * 128 + n], W[(k0 + 1) * 128 + n],
                         W[(k0 + 8) * 128 + n], W[(k0 + 9) * 128 + n]);
}
__global__ void prep3(const float* __restrict__ a2w, int L) {
    int i = blockIdx.x * blockDim.x + threadIdx.x;
    if (i >= L * 8 * 32 * 32) return;
    int lane = i & 31, n8 = (i >> 5) & 31, k16 = (i >> 10) & 7, l = i >> 13;
    int tg = lane & 3, gq = lane >> 2;
    int n = n8 * 8 + gq, k0 = k16 * 16 + tg * 2;
    const float* W = a2w + (size_t)l * 32768;
    g_B3[i] = make_bfrag(W[k0 * 256 + n], W[(k0 + 1) * 256 + n],
                         W[(k0 + 8) * 256 + n], W[(k0 + 9) * 256 + n]);
}

__global__ void zero_out_kernel(float* out, int n) {
    int i = blockIdx.x * blockDim.x + threadIdx.x;
    if (i < n) out[i] = 0.0f;
}

// ---- smem layout (bytes) ----------------------------------------------------
#define SV_S 136                 // [96][128] bf16, stride 136 elems
#define HB_S 264                 // [32][256] bf16
#define AC_S 136                 // [32][128] bf16
#define V1_S 132                 // [96][132] fp32
#define OFF_SVH  0
#define OFF_SVL  (OFF_SVH + 96 * SV_S * 2)
#define OFF_HBH  (OFF_SVL + 96 * SV_S * 2)
#define OFF_HBL  (OFF_HBH + 32 * HB_S * 2)
#define OFF_ACH  (OFF_HBL + 32 * HB_S * 2)
#define OFF_ACL  (OFF_ACH + 32 * AC_S * 2)
#define OFF_V1   (OFF_ACL + 32 * AC_S * 2)
#define OFF_SCS  (OFF_V1 + 96 * V1_S * 4)
#define SM_BYTES (OFF_SCS + 32 * 4)              // 154240

__device__ __forceinline__ uint32_t ldm_addr(uint32_t plane, int row0, int stride,
                                             int lane) {
    return plane + (uint32_t)(((row0 + (lane & 15)) * stride +
                               ((lane >> 4) << 3)) * 2);
}
__device__ __forceinline__ void split_store(char* sm, int offH, int offL,
                                            int row, int stride, int col,
                                            float x0, float x1) {
    uint32_t h, l;
    split_pair(x0, x1, h, l);
    *(uint32_t*)(sm + offH + (row * stride + col) * 2) = h;
    *(uint32_t*)(sm + offL + (row * stride + col) * 2) = l;
}

// ---- fused kernel: 16 warps = 2 ag x 8 ng ----------------------------------
__global__ void __launch_bounds__(THREADS) fused_kernel(
    const float* __restrict__ s_in, const float* __restrict__ v_in,
    const float* __restrict__ mask,
    const float* __restrict__ a1b, const float* __restrict__ a2b,
    const float* __restrict__ out_w, const float* __restrict__ out_b,
    float* __restrict__ out,
    int n_atoms, int n_graphs, int n_layers)
{
    extern __shared__ char sm[];
    const int t = threadIdx.x;
    const int wid = t >> 5, lane = t & 31;
    const int tg = lane & 3, gq = lane >> 2;
    const int ag = wid >> 3, ng = wid & 7;      // 2 x 8
    const int atom0 = blockIdx.x * TB;
    const int na = min(TB, n_atoms - atom0);
    const uint32_t smb = smem_u32(sm);

    float* V1  = (float*)(sm + OFF_V1);
    float* SCS = (float*)(sm + OFF_SCS);

    // ---- load + split input tiles ----
    for (int i = t; i < 96 * 64; i += THREADS) {
        int r = i >> 6, cp = i & 63;
        int c = r >> 5, a = r & 31;
        float2 v = make_float2(0.f, 0.f);
        if (a < na)
            v = *(const float2*)(v_in + (((size_t)(atom0 + a)) * 3 + c) * F + 2 * cp);
        split_store(sm, OFF_SVH, OFF_SVL, r, SV_S, 2 * cp, v.x, v.y);
    }
    for (int i = t; i < 32 * 64; i += THREADS) {
        int a = i >> 6, cp = i & 63;
        float2 v = make_float2(0.f, 0.f);
        if (a < na)
            v = *(const float2*)(s_in + (size_t)(atom0 + a) * F + 2 * cp);
        split_store(sm, OFF_HBH, OFF_HBL, a, HB_S, 2 * cp, v.x, v.y);
    }
    __syncthreads();

    for (int l = 0; l < n_layers; l++) {
        // ===== GEMM1: [96x128] @ [128x256]; k16 outer, c inner (B reuse) =====
        {
            const uint4* B1 = g_B1 + (size_t)l * 8 * 32 * 32;
            float acc[3][4][4];                 // [c][n8][frag]
            #pragma unroll
            for (int c = 0; c < 3; c++)
                #pragma unroll
                for (int n8 = 0; n8 < 4; n8++)
                    #pragma unroll
                    for (int j = 0; j < 4; j++) acc[c][n8][j] = 0.0f;

            #pragma unroll
            for (int k16 = 0; k16 < 8; k16++) {
                uint32_t Ah[3][4], Al[3][4];
                #pragma unroll
                for (int c = 0; c < 3; c++) {
                    const int arow = c * 32 + ag * 16;
                    ldm_x4(Ah[c], ldm_addr(smb + OFF_SVH, arow, SV_S, lane) + k16 * 32);
                    ldm_x4(Al[c], ldm_addr(smb + OFF_SVL, arow, SV_S, lane) + k16 * 32);
                }
                #pragma unroll
                for (int n8 = 0; n8 < 4; n8++) {
                    uint4 bb = B1[(k16 * 32 + ng * 4 + n8) * 32 + lane];
                    #pragma unroll
                    for (int c = 0; c < 3; c++) {
                        mma_bf16(acc[c][n8], Ah[c], bb.x, bb.y);
                        mma_bf16(acc[c][n8], Ah[c], bb.z, bb.w);
                        mma_bf16(acc[c][n8], Al[c], bb.x, bb.y);
                    }
                }
            }
            if (ng < 4) {       // v1 columns 0..127 -> fp32 smem
                #pragma unroll
                for (int c = 0; c < 3; c++) {
                    const int arow = c * 32 + ag * 16;
                    #pragma unroll
                    for (int n8 = 0; n8 < 4; n8++)
                        #pragma unroll
                        for (int j = 0; j < 4; j++) {
                            int row = arow + gq + ((j >> 1) << 3);
                            int col = ng * 32 + n8 * 8 + tg * 2 + (j & 1);
                            V1[row * V1_S + col] = acc[c][n8][j];
                        }
                }
            } else {            // v2 -> n2 (split) into HB[:,128:256]
                #pragma unroll
                for (int n8 = 0; n8 < 4; n8++)
                    #pragma unroll
                    for (int j = 0; j < 4; j += 2) {
                        int a = ag * 16 + gq + ((j >> 1) << 3);
                        int gcol = (ng - 4) * 32 + n8 * 8 + tg * 2;
                        float q0 = acc[0][n8][j] * acc[0][n8][j] +
                                   acc[1][n8][j] * acc[1][n8][j] +
                                   acc[2][n8][j] * acc[2][n8][j];
                        float q1 = acc[0][n8][j+1] * acc[0][n8][j+1] +
                                   acc[1][n8][j+1] * acc[1][n8][j+1] +
                                   acc[2][n8][j+1] * acc[2][n8][j+1];
                        split_store(sm, OFF_HBH, OFF_HBL, a, HB_S, 128 + gcol,
                                    sqrtf(q0), sqrtf(q1));
                    }
            }
        }
        __syncthreads();

        // ===== GEMM2: [32x256] @ [256x128] -> silu -> ACT ====================
        {
            const uint4* B2 = g_B2 + (size_t)l * 16 * 16 * 32;
            float acc[2][4];
            #pragma unroll
            for (int n8 = 0; n8 < 2; n8++)
                #pragma unroll
                for (int j = 0; j < 4; j++) acc[n8][j] = 0.0f;
            const int arow = ag * 16;
            const uint32_t ah = ldm_addr(smb + OFF_HBH, arow, HB_S, lane);
            const uint32_t al = ldm_addr(smb + OFF_HBL, arow, HB_S, lane);
            #pragma unroll
            for (int k16 = 0; k16 < 16; k16++) {
                uint32_t Ah[4], Al[4];
                ldm_x4(Ah, ah + k16 * 32);
                ldm_x4(Al, al + k16 * 32);
                #pragma unroll
                for (int n8 = 0; n8 < 2; n8++) {
                    uint4 bb = B2[(k16 * 16 + ng * 2 + n8) * 32 + lane];
                    mma_bf16(acc[n8], Ah, bb.x, bb.y);
                    mma_bf16(acc[n8], Ah, bb.z, bb.w);
                    mma_bf16(acc[n8], Al, bb.x, bb.y);
                }
            }
            #pragma unroll
            for (int n8 = 0; n8 < 2; n8++)
                #pragma unroll
                for (int j = 0; j < 4; j += 2) {
                    int a = arow + gq + ((j >> 1) << 3);
                    int col = ng * 16 + n8 * 8 + tg * 2;
                    float x0 = acc[n8][j]     + a1b[l * F + col];
                    float x1 = acc[n8][j + 1] + a1b[l * F + col + 1];
                    x0 = x0 / (1.0f + expf(-x0));
                    x1 = x1 / (1.0f + expf(-x1));
                    split_store(sm, OFF_ACH, OFF_ACL, a, AC_S, col, x0, x1);
                }
        }
        __syncthreads();

        // ===== GEMM3: [32x128] @ [128x256] -> s_out | gate ===================
        {
            const uint4* B3 = g_B3 + (size_t)l * 8 * 32 * 32;
            float acc[4][4];
            #pragma unroll
            for (int n8 = 0; n8 < 4; n8++)
                #pragma unroll
                for (int j = 0; j < 4; j++) acc[n8][j] = 0.0f;
            const int arow = ag * 16;
            const uint32_t ah = ldm_addr(smb + OFF_ACH, arow, AC_S, lane);
            const uint32_t al = ldm_addr(smb + OFF_ACL, arow, AC_S, lane);
            #pragma unroll
            for (int k16 = 0; k16 < 8; k16++) {
                uint32_t Ah[4], Al[4];
                ldm_x4(Ah, ah + k16 * 32);
                ldm_x4(Al, al + k16 * 32);
                #pragma unroll
                for (int n8 = 0; n8 < 4; n8++) {
                    uint4 bb = B3[(k16 * 32 + ng * 4 + n8) * 32 + lane];
                    mma_bf16(acc[n8], Ah, bb.x, bb.y);
                    mma_bf16(acc[n8], Ah, bb.z, bb.w);
                    mma_bf16(acc[n8], Al, bb.x, bb.y);
                }
            }
            #pragma unroll
            for (int n8 = 0; n8 < 4; n8++)
                #pragma unroll
                for (int j = 0; j < 4; j += 2) {
                    int a = arow + gq + ((j >> 1) << 3);
                    int col = ng * 32 + n8 * 8 + tg * 2;
                    float x0 = acc[n8][j]     + a2b[l * 256 + col];
                    float x1 = acc[n8][j + 1] + a2b[l * 256 + col + 1];
                    if (col < 128) {
                        split_store(sm, OFF_HBH, OFF_HBL, a, HB_S, col, x0, x1);
                    } else {
                        int gcol = col - 128;
                        #pragma unroll
                        for (int c = 0; c < 3; c++) {
                            int row = c * 32 + a;
                            float p0 = x0 * V1[row * V1_S + gcol];
                            float p1 = x1 * V1[row * V1_S + gcol + 1];
                            split_store(sm, OFF_SVH, OFF_SVL, row, SV_S, gcol, p0, p1);
                        }
                    }
                }
        }
        __syncthreads();
    }

    // ---- sc[a] = dot(s[a], out_w) + ob (16 warps x 2 atoms) ----
    {
        const uint16_t* HH = (const uint16_t*)(sm + OFF_HBH);
        const uint16_t* HL = (const uint16_t*)(sm + OFF_HBL);
        float ow0 = out_w[lane], ow1 = out_w[lane + 32];
        float ow2 = out_w[lane + 64], ow3 = out_w[lane + 96];
        #pragma unroll
        for (int ai = 0; ai < 2; ai++) {
            int a = wid * 2 + ai;
            const uint16_t* rh = HH + a * HB_S;
            const uint16_t* rl = HL + a * HB_S;
            float s0 = __bfloat162float(*(__nv_bfloat16*)&rh[lane]) +
                       __bfloat162float(*(__nv_bfloat16*)&rl[lane]);
            float s1 = __bfloat162float(*(__nv_bfloat16*)&rh[lane + 32]) +
                       __bfloat162float(*(__nv_bfloat16*)&rl[lane + 32]);
            float s2 = __bfloat162float(*(__nv_bfloat16*)&rh[lane + 64]) +
                       __bfloat162float(*(__nv_bfloat16*)&rl[lane + 64]);
            float s3 = __bfloat162float(*(__nv_bfloat16*)&rh[lane + 96]) +
                       __bfloat162float(*(__nv_bfloat16*)&rl[lane + 96]);
            float acc = s0 * ow0 + s1 * ow1 + s2 * ow2 + s3 * ow3;
            #pragma unroll
            for (int off = 16; off > 0; off >>= 1)
                acc += __shfl_xor_sync(0xffffffff, acc, off);
            if (lane == 0) SCS[a] = acc + out_b[0];
        }
    }
    __syncthreads();

    // ---- masked segment sum ----
    for (int b = t; b < n_graphs; b += THREADS) {
        float acc = 0.0f;
        const float* mrow = mask + (size_t)b * n_atoms + atom0;
        for (int a = 0; a < na; a++)
            acc = fmaf(SCS[a], mrow[a], acc);
        atomicAdd(&out[b], acc);
    }
}

// ---- host ------------------------------------------------------------------
extern "C" void kernel_launch(void* const* d_in, const int* in_sizes, int n_in,
                              void* d_out, int out_size) {
    const float* s    = (const float*)d_in[0];
    const float* v    = (const float*)d_in[1];
    const float* mask = (const float*)d_in[3];
    const float* w1   = (const float*)d_in[4];
    const float* w2   = (const float*)d_in[5];
    const float* a1w  = (const float*)d_in[6];
    const float* a1b  = (const float*)d_in[7];
    const float* a2w  = (const float*)d_in[8];
    const float* a2b  = (const float*)d_in[9];
    const float* ow   = (const float*)d_in[10];
    const float* ob   = (const float*)d_in[11];
    float* out = (float*)d_out;

    const int NA = in_sizes[0] / F;
    const int L  = in_sizes[7] / F;
    const int NG = out_size;

    cudaFuncSetAttribute(fused_kernel, cudaFuncAttributeMaxDynamicSharedMemorySize,
                         SM_BYTES);

    prep1<<<(L * 8192 + 255) / 256, 256>>>(w1, w2, L);
    prep2<<<(L * 8192 + 255) / 256, 256>>>(a1w, L);
    prep3<<<(L * 8192 + 255) / 256, 256>>>(a2w, L);
    zero_out_kernel<<<(out_size + 127) / 128, 128>>>(out, out_size);

    int grid = (NA + TB - 1) / TB;
    fused_kernel<<<grid, THREADS, SM_BYTES>>>(s, v, mask, a1b, a2b, ow, ob, out,
                                              NA, NG, L);
}

// round 8
// speedup vs baseline: 3.0588x; 1.0260x over previous
#include <cuda_runtime.h>
#include <cuda_bf16.h>
#include <stdint.h>
#include <math.h>

#define F 128
#define TB 32            // atoms per block
#define THREADS 512
#define LMAX 2

// ---- precomputed weight fragments (uint4 = {bh0,bh1,bl0,bl1}) --------------
__device__ uint4 g_B1[LMAX * 8 * 32 * 32];    // GEMM1: K=128(8 k16), N=256(32 n8)
__device__ uint4 g_B2[LMAX * 16 * 16 * 32];   // GEMM2: K=256, N=128
__device__ uint4 g_B3[LMAX * 8 * 32 * 32];    // GEMM3: K=128, N=256

// ---- helpers ---------------------------------------------------------------
__device__ __forceinline__ uint32_t pack_bf(float x, float y) {
    __nv_bfloat16 hx = __float2bfloat16(x), hy = __float2bfloat16(y);
    uint16_t ux = *(uint16_t*)&hx, uy = *(uint16_t*)&hy;
    return (uint32_t)ux | ((uint32_t)uy << 16);
}
__device__ __forceinline__ void split_pair(float x, float y,
                                           uint32_t& hi, uint32_t& lo) {
    __nv_bfloat16 hx = __float2bfloat16(x), hy = __float2bfloat16(y);
    float fx = __bfloat162float(hx), fy = __bfloat162float(hy);
    uint16_t ux = *(uint16_t*)&hx, uy = *(uint16_t*)&hy;
    hi = (uint32_t)ux | ((uint32_t)uy << 16);
    lo = pack_bf(x - fx, y - fy);
}
__device__ __forceinline__ void mma_bf16(float* d, const uint32_t* a,
                                         uint32_t b0, uint32_t b1) {
    asm volatile(
        "mma.sync.aligned.m16n8k16.row.col.f32.bf16.bf16.f32 "
        "{%0,%1,%2,%3}, {%4,%5,%6,%7}, {%8,%9}, {%0,%1,%2,%3};"
        : "+f"(d[0]), "+f"(d[1]), "+f"(d[2]), "+f"(d[3])
        : "r"(a[0]), "r"(a[1]), "r"(a[2]), "r"(a[3]), "r"(b0), "r"(b1));
}
__device__ __forceinline__ void ldm_x4(uint32_t* r, uint32_t addr) {
    asm volatile("ldmatrix.sync.aligned.m8n8.x4.shared.b16 {%0,%1,%2,%3}, [%4];"
        : "=r"(r[0]), "=r"(r[1]), "=r"(r[2]), "=r"(r[3]) : "r"(addr));
}
__device__ __forceinline__ uint32_t smem_u32(const void* p) {
    uint32_t a;
    asm("{ .reg .u64 t; cvta.to.shared.u64 t, %1; cvt.u32.u64 %0, t; }"
        : "=r"(a) : "l"(p));
    return a;
}

// ---- weight prep kernels ---------------------------------------------------
__device__ __forceinline__ uint4 make_bfrag(float k0v, float k1v, float k8v, float k9v) {
    uint4 r;
    uint32_t h0, l0, h1, l1;
    split_pair(k0v, k1v, h0, l0);
    split_pair(k8v, k9v, h1, l1);
    r.x = h0; r.y = h1; r.z = l0; r.w = l1;
    return r;
}
__global__ void prep1(const float* __restrict__ w1, const float* __restrict__ w2, int L) {
    int i = blockIdx.x * blockDim.x + threadIdx.x;
    if (i >= L * 8 * 32 * 32) return;
    int lane = i & 31, n8 = (i >> 5) & 31, k16 = (i >> 10) & 7, l = i >> 13;
    int tg = lane & 3, gq = lane >> 2;
    int n = n8 * 8 + gq, k0 = k16 * 16 + tg * 2;
    const float* W = (n < 128) ? (w1 + (size_t)l * 16384) : (w2 + (size_t)l * 16384);
    int nn = n & 127;
    g_B1[i] = make_bfrag(W[k0 * 128 + nn], W[(k0 + 1) * 128 + nn],
                         W[(k0 + 8) * 128 + nn], W[(k0 + 9) * 128 + nn]);
}
__global__ void prep2(const float* __restrict__ a1w, int L) {
    int i = blockIdx.x * blockDim.x + threadIdx.x;
    if (i >= L * 16 * 16 * 32) return;
    int lane = i & 31, n8 = (i >> 5) & 15, k16 = (i >> 9) & 15, l = i >> 13;
    int tg = lane & 3, gq = lane >> 2;
    int n = n8 * 8 + gq, k0 = k16 * 16 + tg * 2;
    const float* W = a1w + (size_t)l * 32768;
    g_B2[i] = make_bfrag(W[k0 * 128 + n], W[(k0 + 1) * 128 + n],
                         W[(k0 + 8) * 128 + n], W[(k0 + 9) * 128 + n]);
}
__global__ void prep3(const float* __restrict__ a2w, int L) {
    int i = blockIdx.x * blockDim.x + threadIdx.x;
    if (i >= L * 8 * 32 * 32) return;
    int lane = i & 31, n8 = (i >> 5) & 31, k16 = (i >> 10) & 7, l = i >> 13;
    int tg = lane & 3, gq = lane >> 2;
    int n = n8 * 8 + gq, k0 = k16 * 16 + tg * 2;
    const float* W = a2w + (size_t)l * 32768;
    g_B3[i] = make_bfrag(W[k0 * 256 + n], W[(k0 + 1) * 256 + n],
                         W[(k0 + 8) * 256 + n], W[(k0 + 9) * 256 + n]);
}

__global__ void zero_half_kernel(float* out, int base, int n) {
    int i = blockIdx.x * blockDim.x + threadIdx.x;
    if (i < n) out[base + i] = 0.0f;
}

// ---- smem layout (bytes) ----------------------------------------------------
#define SV_S 136                 // [96][128] bf16, stride 136 elems
#define HB_S 264                 // [32][256] bf16
#define AC_S 136                 // [32][128] bf16
#define OFF_SVH  0
#define OFF_SVL  (OFF_SVH + 96 * SV_S * 2)
#define OFF_HBH  (OFF_SVL + 96 * SV_S * 2)
#define OFF_HBL  (OFF_HBH + 32 * HB_S * 2)
#define OFF_ACH  (OFF_HBL + 32 * HB_S * 2)
#define OFF_ACL  (OFF_ACH + 32 * AC_S * 2)
#define OFF_SCS  (OFF_ACL + 32 * AC_S * 2)
#define SM_BYTES (OFF_SCS + 32 * 4)              // ~103.6 KB

__device__ __forceinline__ uint32_t ldm_addr(uint32_t plane, int row0, int stride,
                                             int lane) {
    return plane + (uint32_t)(((row0 + (lane & 15)) * stride +
                               ((lane >> 4) << 3)) * 2);
}
__device__ __forceinline__ void split_store(char* sm, int offH, int offL,
                                            int row, int stride, int col,
                                            float x0, float x1) {
    uint32_t h, l;
    split_pair(x0, x1, h, l);
    *(uint32_t*)(sm + offH + (row * stride + col) * 2) = h;
    *(uint32_t*)(sm + offL + (row * stride + col) * 2) = l;
}

// ---- fused kernel: 16 warps = 2 ag x 8 ng ----------------------------------
// ng<4 warps: own v1 (GEMM1 cols 0-127) in regs, compute GEMM3 gate cols
// (128-255), gate in-register. ng>=4 warps: v2->n2, GEMM3 s cols (0-127).
__global__ void __launch_bounds__(THREADS) fused_kernel(
    const float* __restrict__ s_in, const float* __restrict__ v_in,
    const float* __restrict__ mask,
    const float* __restrict__ a1b, const float* __restrict__ a2b,
    const float* __restrict__ out_w, const float* __restrict__ out_b,
    float* __restrict__ out,
    int n_atoms, int n_graphs, int n_layers)
{
    extern __shared__ char sm[];
    const int t = threadIdx.x;
    const int wid = t >> 5, lane = t & 31;
    const int tg = lane & 3, gq = lane >> 2;
    const int ag = wid >> 3, ng = wid & 7;      // 2 x 8
    const int atom0 = blockIdx.x * TB;
    const int na = min(TB, n_atoms - atom0);
    const uint32_t smb = smem_u32(sm);

    float* SCS = (float*)(sm + OFF_SCS);

    // ---- load + split input tiles ----
    for (int i = t; i < 96 * 64; i += THREADS) {
        int r = i >> 6, cp = i & 63;
        int c = r >> 5, a = r & 31;
        float2 v = make_float2(0.f, 0.f);
        if (a < na)
            v = *(const float2*)(v_in + (((size_t)(atom0 + a)) * 3 + c) * F + 2 * cp);
        split_store(sm, OFF_SVH, OFF_SVL, r, SV_S, 2 * cp, v.x, v.y);
    }
    for (int i = t; i < 32 * 64; i += THREADS) {
        int a = i >> 6, cp = i & 63;
        float2 v = make_float2(0.f, 0.f);
        if (a < na)
            v = *(const float2*)(s_in + (size_t)(atom0 + a) * F + 2 * cp);
        split_store(sm, OFF_HBH, OFF_HBL, a, HB_S, 2 * cp, v.x, v.y);
    }
    __syncthreads();

    for (int l = 0; l < n_layers; l++) {
        // GEMM1 accumulators (ng<4: v1, kept live until GEMM3; ng>=4: v2)
        float acc1[3][4][4];
        #pragma unroll
        for (int c = 0; c < 3; c++)
            #pragma unroll
            for (int n8 = 0; n8 < 4; n8++)
                #pragma unroll
                for (int j = 0; j < 4; j++) acc1[c][n8][j] = 0.0f;

        // ===== GEMM1: [96x128] @ [128x256]; k16 outer, c inner (B reuse) =====
        {
            const uint4* B1 = g_B1 + (size_t)l * 8 * 32 * 32;
            #pragma unroll
            for (int k16 = 0; k16 < 8; k16++) {
                uint32_t Ah[3][4], Al[3][4];
                #pragma unroll
                for (int c = 0; c < 3; c++) {
                    const int arow = c * 32 + ag * 16;
                    ldm_x4(Ah[c], ldm_addr(smb + OFF_SVH, arow, SV_S, lane) + k16 * 32);
                    ldm_x4(Al[c], ldm_addr(smb + OFF_SVL, arow, SV_S, lane) + k16 * 32);
                }
                #pragma unroll
                for (int n8 = 0; n8 < 4; n8++) {
                    uint4 bb = B1[(k16 * 32 + ng * 4 + n8) * 32 + lane];
                    #pragma unroll
                    for (int c = 0; c < 3; c++) {
                        mma_bf16(acc1[c][n8], Ah[c], bb.x, bb.y);
                        mma_bf16(acc1[c][n8], Ah[c], bb.z, bb.w);
                        mma_bf16(acc1[c][n8], Al[c], bb.x, bb.y);
                    }
                }
            }
            if (ng >= 4) {      // v2 -> n2 (split) into HB[:,128:256]
                #pragma unroll
                for (int n8 = 0; n8 < 4; n8++)
                    #pragma unroll
                    for (int j = 0; j < 4; j += 2) {
                        int a = ag * 16 + gq + ((j >> 1) << 3);
                        int gcol = (ng - 4) * 32 + n8 * 8 + tg * 2;
                        float q0 = acc1[0][n8][j] * acc1[0][n8][j] +
                                   acc1[1][n8][j] * acc1[1][n8][j] +
                                   acc1[2][n8][j] * acc1[2][n8][j];
                        float q1 = acc1[0][n8][j+1] * acc1[0][n8][j+1] +
                                   acc1[1][n8][j+1] * acc1[1][n8][j+1] +
                                   acc1[2][n8][j+1] * acc1[2][n8][j+1];
                        split_store(sm, OFF_HBH, OFF_HBL, a, HB_S, 128 + gcol,
                                    sqrtf(q0), sqrtf(q1));
                    }
            }
            // ng<4: v1 stays in acc1 registers
        }
        __syncthreads();

        // ===== GEMM2: [32x256] @ [256x128] -> silu -> ACT ====================
        {
            const uint4* B2 = g_B2 + (size_t)l * 16 * 16 * 32;
            float acc[2][4];
            #pragma unroll
            for (int n8 = 0; n8 < 2; n8++)
                #pragma unroll
                for (int j = 0; j < 4; j++) acc[n8][j] = 0.0f;
            const int arow = ag * 16;
            const uint32_t ah = ldm_addr(smb + OFF_HBH, arow, HB_S, lane);
            const uint32_t al = ldm_addr(smb + OFF_HBL, arow, HB_S, lane);
            #pragma unroll
            for (int k16 = 0; k16 < 16; k16++) {
                uint32_t Ah[4], Al[4];
                ldm_x4(Ah, ah + k16 * 32);
                ldm_x4(Al, al + k16 * 32);
                #pragma unroll
                for (int n8 = 0; n8 < 2; n8++) {
                    uint4 bb = B2[(k16 * 16 + ng * 2 + n8) * 32 + lane];
                    mma_bf16(acc[n8], Ah, bb.x, bb.y);
                    mma_bf16(acc[n8], Ah, bb.z, bb.w);
                    mma_bf16(acc[n8], Al, bb.x, bb.y);
                }
            }
            #pragma unroll
            for (int n8 = 0; n8 < 2; n8++)
                #pragma unroll
                for (int j = 0; j < 4; j += 2) {
                    int a = arow + gq + ((j >> 1) << 3);
                    int col = ng * 16 + n8 * 8 + tg * 2;
                    float x0 = acc[n8][j]     + a1b[l * F + col];
                    float x1 = acc[n8][j + 1] + a1b[l * F + col + 1];
                    x0 = x0 / (1.0f + __expf(-x0));
                    x1 = x1 / (1.0f + __expf(-x1));
                    split_store(sm, OFF_ACH, OFF_ACL, a, AC_S, col, x0, x1);
                }
        }
        __syncthreads();

        // ===== GEMM3: [32x128] @ [128x256] ===================================
        // ng<4 -> gate cols 128+ng*32.. (gating in-register with acc1)
        // ng>=4 -> s cols (ng-4)*32..
        {
            const uint4* B3 = g_B3 + (size_t)l * 8 * 32 * 32;
            const int nb0 = (ng < 4) ? (16 + ng * 4) : ((ng - 4) * 4);
            float acc[4][4];
            #pragma unroll
            for (int n8 = 0; n8 < 4; n8++)
                #pragma unroll
                for (int j = 0; j < 4; j++) acc[n8][j] = 0.0f;
            const int arow = ag * 16;
            const uint32_t ah = ldm_addr(smb + OFF_ACH, arow, AC_S, lane);
            const uint32_t al = ldm_addr(smb + OFF_ACL, arow, AC_S, lane);
            #pragma unroll
            for (int k16 = 0; k16 < 8; k16++) {
                uint32_t Ah[4], Al[4];
                ldm_x4(Ah, ah + k16 * 32);
                ldm_x4(Al, al + k16 * 32);
                #pragma unroll
                for (int n8 = 0; n8 < 4; n8++) {
                    uint4 bb = B3[(k16 * 32 + nb0 + n8) * 32 + lane];
                    mma_bf16(acc[n8], Ah, bb.x, bb.y);
                    mma_bf16(acc[n8], Ah, bb.z, bb.w);
                    mma_bf16(acc[n8], Al, bb.x, bb.y);
                }
            }
            if (ng < 4) {
                // gate = acc + bias; v_out = gate * v1(regs) -> SV planes
                #pragma unroll
                for (int n8 = 0; n8 < 4; n8++)
                    #pragma unroll
                    for (int j = 0; j < 4; j += 2) {
                        int a = arow + gq + ((j >> 1) << 3);
                        int colg = ng * 32 + n8 * 8 + tg * 2;     // 0..127
                        float x0 = acc[n8][j]     + a2b[l * 256 + 128 + colg];
                        float x1 = acc[n8][j + 1] + a2b[l * 256 + 128 + colg + 1];
                        #pragma unroll
                        for (int c = 0; c < 3; c++) {
                            int row = c * 32 + a;
                            float p0 = x0 * acc1[c][n8][j];
                            float p1 = x1 * acc1[c][n8][j + 1];
                            split_store(sm, OFF_SVH, OFF_SVL, row, SV_S, colg, p0, p1);
                        }
                    }
            } else {
                // s_out -> HB planes
                #pragma unroll
                for (int n8 = 0; n8 < 4; n8++)
                    #pragma unroll
                    for (int j = 0; j < 4; j += 2) {
                        int a = arow + gq + ((j >> 1) << 3);
                        int col = (ng - 4) * 32 + n8 * 8 + tg * 2;
                        float x0 = acc[n8][j]     + a2b[l * 256 + col];
                        float x1 = acc[n8][j + 1] + a2b[l * 256 + col + 1];
                        split_store(sm, OFF_HBH, OFF_HBL, a, HB_S, col, x0, x1);
                    }
            }
        }
        __syncthreads();
    }

    // ---- sc[a] = dot(s[a], out_w) + ob (16 warps x 2 atoms) ----
    {
        const uint16_t* HH = (const uint16_t*)(sm + OFF_HBH);
        const uint16_t* HL = (const uint16_t*)(sm + OFF_HBL);
        float ow0 = out_w[lane], ow1 = out_w[lane + 32];
        float ow2 = out_w[lane + 64], ow3 = out_w[lane + 96];
        #pragma unroll
        for (int ai = 0; ai < 2; ai++) {
            int a = wid * 2 + ai;
            const uint16_t* rh = HH + a * HB_S;
            const uint16_t* rl = HL + a * HB_S;
            float s0 = __bfloat162float(*(__nv_bfloat16*)&rh[lane]) +
                       __bfloat162float(*(__nv_bfloat16*)&rl[lane]);
            float s1 = __bfloat162float(*(__nv_bfloat16*)&rh[lane + 32]) +
                       __bfloat162float(*(__nv_bfloat16*)&rl[lane + 32]);
            float s2 = __bfloat162float(*(__nv_bfloat16*)&rh[lane + 64]) +
                       __bfloat162float(*(__nv_bfloat16*)&rl[lane + 64]);
            float s3 = __bfloat162float(*(__nv_bfloat16*)&rh[lane + 96]) +
                       __bfloat162float(*(__nv_bfloat16*)&rl[lane + 96]);
            float acc = s0 * ow0 + s1 * ow1 + s2 * ow2 + s3 * ow3;
            #pragma unroll
            for (int off = 16; off > 0; off >>= 1)
                acc += __shfl_xor_sync(0xffffffff, acc, off);
            if (lane == 0) SCS[a] = acc + out_b[0];
        }
    }
    __syncthreads();

    // ---- masked segment sum ----
    for (int b = t; b < n_graphs; b += THREADS) {
        float acc = 0.0f;
        const float* mrow = mask + (size_t)b * n_atoms + atom0;
        for (int a = 0; a < na; a++)
            acc = fmaf(SCS[a], mrow[a], acc);
        atomicAdd(&out[b], acc);
    }
}

// ---- host ------------------------------------------------------------------
extern "C" void kernel_launch(void* const* d_in, const int* in_sizes, int n_in,
                              void* d_out, int out_size) {
    const float* s    = (const float*)d_in[0];
    const float* v    = (const float*)d_in[1];
    const float* mask = (const float*)d_in[3];
    const float* w1   = (const float*)d_in[4];
    const float* w2   = (const float*)d_in[5];
    const float* a1w  = (const float*)d_in[6];
    const float* a1b  = (const float*)d_in[7];
    const float* a2w  = (const float*)d_in[8];
    const float* a2b  = (const float*)d_in[9];
    const float* ow   = (const float*)d_in[10];
    const float* ob   = (const float*)d_in[11];
    float* out = (float*)d_out;

    const int NA = in_sizes[0] / F;
    const int L  = in_sizes[7] / F;
    const int NG = out_size;

    cudaFuncSetAttribute(fused_kernel, cudaFuncAttributeMaxDynamicSharedMemorySize,
                         SM_BYTES);

    // 6 launches/call -> ncu (-s 5 -c 1) profiles fused_kernel
    prep1<<<(L * 8192 + 255) / 256, 256>>>(w1, w2, L);
    prep2<<<(L * 8192 + 255) / 256, 256>>>(a1w, L);
    prep3<<<(L * 8192 + 255) / 256, 256>>>(a2w, L);
    int h1 = out_size / 2, h2 = out_size - h1;
    zero_half_kernel<<<(h1 + 127) / 128, 128>>>(out, 0, h1);
    zero_half_kernel<<<(h2 + 127) / 128, 128>>>(out, h1, h2);

    int grid = (NA + TB - 1) / TB;
    fused_kernel<<<grid, THREADS, SM_BYTES>>>(s, v, mask, a1b, a2b, ow, ob, out,
                                              NA, NG, L);
}

// round 9
// speedup vs baseline: 3.5832x; 1.1714x over previous
#include <cuda_runtime.h>
#include <cuda_fp16.h>
#include <stdint.h>
#include <math.h>

#define F 128
#define TB 32            // atoms per block
#define THREADS 512
#define LMAX 2

// ---- precomputed weight fragments (uint2 = {bh0,bh1}, fp16 hi only) --------
__device__ uint2 g_B1[LMAX * 8 * 32 * 32];    // GEMM1: K=128(8 k16), N=256(32 n8)
__device__ uint2 g_B2[LMAX * 16 * 16 * 32];   // GEMM2: K=256, N=128
__device__ uint2 g_B3[LMAX * 8 * 32 * 32];    // GEMM3: K=128, N=256

// ---- helpers ---------------------------------------------------------------
__device__ __forceinline__ uint32_t pack_h(float x, float y) {
    __half hx = __float2half_rn(x), hy = __float2half_rn(y);
    uint16_t ux = *(uint16_t*)&hx, uy = *(uint16_t*)&hy;
    return (uint32_t)ux | ((uint32_t)uy << 16);
}
// fp16 split: hi = fp16(x), lo = fp16(x - hi)
__device__ __forceinline__ void split_pair(float x, float y,
                                           uint32_t& hi, uint32_t& lo) {
    __half hx = __float2half_rn(x), hy = __float2half_rn(y);
    float fx = __half2float(hx), fy = __half2float(hy);
    uint16_t ux = *(uint16_t*)&hx, uy = *(uint16_t*)&hy;
    hi = (uint32_t)ux | ((uint32_t)uy << 16);
    lo = pack_h(x - fx, y - fy);
}
__device__ __forceinline__ void mma_f16(float* d, const uint32_t* a,
                                        uint32_t b0, uint32_t b1) {
    asm volatile(
        "mma.sync.aligned.m16n8k16.row.col.f32.f16.f16.f32 "
        "{%0,%1,%2,%3}, {%4,%5,%6,%7}, {%8,%9}, {%0,%1,%2,%3};"
        : "+f"(d[0]), "+f"(d[1]), "+f"(d[2]), "+f"(d[3])
        : "r"(a[0]), "r"(a[1]), "r"(a[2]), "r"(a[3]), "r"(b0), "r"(b1));
}
__device__ __forceinline__ void ldm_x4(uint32_t* r, uint32_t addr) {
    asm volatile("ldmatrix.sync.aligned.m8n8.x4.shared.b16 {%0,%1,%2,%3}, [%4];"
        : "=r"(r[0]), "=r"(r[1]), "=r"(r[2]), "=r"(r[3]) : "r"(addr));
}
__device__ __forceinline__ uint32_t smem_u32(const void* p) {
    uint32_t a;
    asm("{ .reg .u64 t; cvta.to.shared.u64 t, %1; cvt.u32.u64 %0, t; }"
        : "=r"(a) : "l"(p));
    return a;
}

// ---- weight prep kernels (fp16 hi plane only) ------------------------------
__device__ __forceinline__ uint2 make_bfrag(float k0v, float k1v, float k8v, float k9v) {
    uint2 r;
    r.x = pack_h(k0v, k1v);
    r.y = pack_h(k8v, k9v);
    return r;
}
__global__ void prep1(const float* __restrict__ w1, const float* __restrict__ w2, int L) {
    int i = blockIdx.x * blockDim.x + threadIdx.x;
    if (i >= L * 8 * 32 * 32) return;
    int lane = i & 31, n8 = (i >> 5) & 31, k16 = (i >> 10) & 7, l = i >> 13;
    int tg = lane & 3, gq = lane >> 2;
    int n = n8 * 8 + gq, k0 = k16 * 16 + tg * 2;
    const float* W = (n < 128) ? (w1 + (size_t)l * 16384) : (w2 + (size_t)l * 16384);
    int nn = n & 127;
    g_B1[i] = make_bfrag(W[k0 * 128 + nn], W[(k0 + 1) * 128 + nn],
                         W[(k0 + 8) * 128 + nn], W[(k0 + 9) * 128 + nn]);
}
__global__ void prep2(const float* __restrict__ a1w, int L) {
    int i = blockIdx.x * blockDim.x + threadIdx.x;
    if (i >= L * 16 * 16 * 32) return;
    int lane = i & 31, n8 = (i >> 5) & 15, k16 = (i >> 9) & 15, l = i >> 13;
    int tg = lane & 3, gq = lane >> 2;
    int n = n8 * 8 + gq, k0 = k16 * 16 + tg * 2;
    const float* W = a1w + (size_t)l * 32768;
    g_B2[i] = make_bfrag(W[k0 * 128 + n], W[(k0 + 1) * 128 + n],
                         W[(k0 + 8) * 128 + n], W[(k0 + 9) * 128 + n]);
}
__global__ void prep3(const float* __restrict__ a2w, int L) {
    int i = blockIdx.x * blockDim.x + threadIdx.x;
    if (i >= L * 8 * 32 * 32) return;
    int lane = i & 31, n8 = (i >> 5) & 31, k16 = (i >> 10) & 7, l = i >> 13;
    int tg = lane & 3, gq = lane >> 2;
    int n = n8 * 8 + gq, k0 = k16 * 16 + tg * 2;
    const float* W = a2w + (size_t)l * 32768;
    g_B3[i] = make_bfrag(W[k0 * 256 + n], W[(k0 + 1) * 256 + n],
                         W[(k0 + 8) * 256 + n], W[(k0 + 9) * 256 + n]);
}

__global__ void zero_half_kernel(float* out, int base, int n) {
    int i = blockIdx.x * blockDim.x + threadIdx.x;
    if (i < n) out[base + i] = 0.0f;
}

// ---- smem layout (bytes) ----------------------------------------------------
#define SV_S 136                 // [96][128] fp16, stride 136 elems
#define HB_S 264                 // [32][256] fp16
#define AC_S 136                 // [32][128] fp16
#define OFF_SVH  0
#define OFF_SVL  (OFF_SVH + 96 * SV_S * 2)
#define OFF_HBH  (OFF_SVL + 96 * SV_S * 2)
#define OFF_HBL  (OFF_HBH + 32 * HB_S * 2)
#define OFF_ACH  (OFF_HBL + 32 * HB_S * 2)
#define OFF_ACL  (OFF_ACH + 32 * AC_S * 2)
#define OFF_SCS  (OFF_ACL + 32 * AC_S * 2)
#define SM_BYTES (OFF_SCS + 32 * 4)              // ~103.6 KB

__device__ __forceinline__ uint32_t ldm_addr(uint32_t plane, int row0, int stride,
                                             int lane) {
    return plane + (uint32_t)(((row0 + (lane & 15)) * stride +
                               ((lane >> 4) << 3)) * 2);
}
__device__ __forceinline__ void split_store(char* sm, int offH, int offL,
                                            int row, int stride, int col,
                                            float x0, float x1) {
    uint32_t h, l;
    split_pair(x0, x1, h, l);
    *(uint32_t*)(sm + offH + (row * stride + col) * 2) = h;
    *(uint32_t*)(sm + offL + (row * stride + col) * 2) = l;
}

// ---- fused kernel: 16 warps = 2 ag x 8 ng ----------------------------------
// ng<4 warps: own v1 (GEMM1 cols 0-127) in regs, compute GEMM3 gate cols
// (128-255), gate in-register. ng>=4 warps: v2->n2, GEMM3 s cols (0-127).
__global__ void __launch_bounds__(THREADS) fused_kernel(
    const float* __restrict__ s_in, const float* __restrict__ v_in,
    const float* __restrict__ mask,
    const float* __restrict__ a1b, const float* __restrict__ a2b,
    const float* __restrict__ out_w, const float* __restrict__ out_b,
    float* __restrict__ out,
    int n_atoms, int n_graphs, int n_layers)
{
    extern __shared__ char sm[];
    const int t = threadIdx.x;
    const int wid = t >> 5, lane = t & 31;
    const int tg = lane & 3, gq = lane >> 2;
    const int ag = wid >> 3, ng = wid & 7;      // 2 x 8
    const int atom0 = blockIdx.x * TB;
    const int na = min(TB, n_atoms - atom0);
    const uint32_t smb = smem_u32(sm);

    float* SCS = (float*)(sm + OFF_SCS);

    // ---- load + split input tiles ----
    for (int i = t; i < 96 * 64; i += THREADS) {
        int r = i >> 6, cp = i & 63;
        int c = r >> 5, a = r & 31;
        float2 v = make_float2(0.f, 0.f);
        if (a < na)
            v = *(const float2*)(v_in + (((size_t)(atom0 + a)) * 3 + c) * F + 2 * cp);
        split_store(sm, OFF_SVH, OFF_SVL, r, SV_S, 2 * cp, v.x, v.y);
    }
    for (int i = t; i < 32 * 64; i += THREADS) {
        int a = i >> 6, cp = i & 63;
        float2 v = make_float2(0.f, 0.f);
        if (a < na)
            v = *(const float2*)(s_in + (size_t)(atom0 + a) * F + 2 * cp);
        split_store(sm, OFF_HBH, OFF_HBL, a, HB_S, 2 * cp, v.x, v.y);
    }
    __syncthreads();

    for (int l = 0; l < n_layers; l++) {
        // GEMM1 accumulators (ng<4: v1, kept live until GEMM3; ng>=4: v2)
        float acc1[3][4][4];
        #pragma unroll
        for (int c = 0; c < 3; c++)
            #pragma unroll
            for (int n8 = 0; n8 < 4; n8++)
                #pragma unroll
                for (int j = 0; j < 4; j++) acc1[c][n8][j] = 0.0f;

        // ===== GEMM1: [96x128] @ [128x256]; k16 outer, c inner (B reuse) =====
        {
            const uint2* B1 = g_B1 + (size_t)l * 8 * 32 * 32;
            #pragma unroll
            for (int k16 = 0; k16 < 8; k16++) {
                uint32_t Ah[3][4], Al[3][4];
                #pragma unroll
                for (int c = 0; c < 3; c++) {
                    const int arow = c * 32 + ag * 16;
                    ldm_x4(Ah[c], ldm_addr(smb + OFF_SVH, arow, SV_S, lane) + k16 * 32);
                    ldm_x4(Al[c], ldm_addr(smb + OFF_SVL, arow, SV_S, lane) + k16 * 32);
                }
                #pragma unroll
                for (int n8 = 0; n8 < 4; n8++) {
                    uint2 bb = B1[(k16 * 32 + ng * 4 + n8) * 32 + lane];
                    #pragma unroll
                    for (int c = 0; c < 3; c++) {
                        mma_f16(acc1[c][n8], Ah[c], bb.x, bb.y);
                        mma_f16(acc1[c][n8], Al[c], bb.x, bb.y);
                    }
                }
            }
            if (ng >= 4) {      // v2 -> n2 (split) into HB[:,128:256]
                #pragma unroll
                for (int n8 = 0; n8 < 4; n8++)
                    #pragma unroll
                    for (int j = 0; j < 4; j += 2) {
                        int a = ag * 16 + gq + ((j >> 1) << 3);
                        int gcol = (ng - 4) * 32 + n8 * 8 + tg * 2;
                        float q0 = acc1[0][n8][j] * acc1[0][n8][j] +
                                   acc1[1][n8][j] * acc1[1][n8][j] +
                                   acc1[2][n8][j] * acc1[2][n8][j];
                        float q1 = acc1[0][n8][j+1] * acc1[0][n8][j+1] +
                                   acc1[1][n8][j+1] * acc1[1][n8][j+1] +
                                   acc1[2][n8][j+1] * acc1[2][n8][j+1];
                        split_store(sm, OFF_HBH, OFF_HBL, a, HB_S, 128 + gcol,
                                    sqrtf(q0), sqrtf(q1));
                    }
            }
            // ng<4: v1 stays in acc1 registers
        }
        __syncthreads();

        // ===== GEMM2: [32x256] @ [256x128] -> silu -> ACT ====================
        {
            const uint2* B2 = g_B2 + (size_t)l * 16 * 16 * 32;
            float acc[2][4];
            #pragma unroll
            for (int n8 = 0; n8 < 2; n8++)
                #pragma unroll
                for (int j = 0; j < 4; j++) acc[n8][j] = 0.0f;
            const int arow = ag * 16;
            const uint32_t ah = ldm_addr(smb + OFF_HBH, arow, HB_S, lane);
            const uint32_t al = ldm_addr(smb + OFF_HBL, arow, HB_S, lane);
            #pragma unroll
            for (int k16 = 0; k16 < 16; k16++) {
                uint32_t Ah[4], Al[4];
                ldm_x4(Ah, ah + k16 * 32);
                ldm_x4(Al, al + k16 * 32);
                #pragma unroll
                for (int n8 = 0; n8 < 2; n8++) {
                    uint2 bb = B2[(k16 * 16 + ng * 2 + n8) * 32 + lane];
                    mma_f16(acc[n8], Ah, bb.x, bb.y);
                    mma_f16(acc[n8], Al, bb.x, bb.y);
                }
            }
            #pragma unroll
            for (int n8 = 0; n8 < 2; n8++)
                #pragma unroll
                for (int j = 0; j < 4; j += 2) {
                    int a = arow + gq + ((j >> 1) << 3);
                    int col = ng * 16 + n8 * 8 + tg * 2;
                    float x0 = acc[n8][j]     + a1b[l * F + col];
                    float x1 = acc[n8][j + 1] + a1b[l * F + col + 1];
                    x0 = x0 / (1.0f + __expf(-x0));
                    x1 = x1 / (1.0f + __expf(-x1));
                    split_store(sm, OFF_ACH, OFF_ACL, a, AC_S, col, x0, x1);
                }
        }
        __syncthreads();

        // ===== GEMM3: [32x128] @ [128x256] ===================================
        // ng<4 -> gate cols 128+ng*32.. (gating in-register with acc1)
        // ng>=4 -> s cols (ng-4)*32..
        {
            const uint2* B3 = g_B3 + (size_t)l * 8 * 32 * 32;
            const int nb0 = (ng < 4) ? (16 + ng * 4) : ((ng - 4) * 4);
            float acc[4][4];
            #pragma unroll
            for (int n8 = 0; n8 < 4; n8++)
                #pragma unroll
                for (int j = 0; j < 4; j++) acc[n8][j] = 0.0f;
            const int arow = ag * 16;
            const uint32_t ah = ldm_addr(smb + OFF_ACH, arow, AC_S, lane);
            const uint32_t al = ldm_addr(smb + OFF_ACL, arow, AC_S, lane);
            #pragma unroll
            for (int k16 = 0; k16 < 8; k16++) {
                uint32_t Ah[4], Al[4];
                ldm_x4(Ah, ah + k16 * 32);
                ldm_x4(Al, al + k16 * 32);
                #pragma unroll
                for (int n8 = 0; n8 < 4; n8++) {
                    uint2 bb = B3[(k16 * 32 + nb0 + n8) * 32 + lane];
                    mma_f16(acc[n8], Ah, bb.x, bb.y);
                    mma_f16(acc[n8], Al, bb.x, bb.y);
                }
            }
            if (ng < 4) {
                // gate = acc + bias; v_out = gate * v1(regs) -> SV planes
                #pragma unroll
                for (int n8 = 0; n8 < 4; n8++)
                    #pragma unroll
                    for (int j = 0; j < 4; j += 2) {
                        int a = arow + gq + ((j >> 1) << 3);
                        int colg = ng * 32 + n8 * 8 + tg * 2;     // 0..127
                        float x0 = acc[n8][j]     + a2b[l * 256 + 128 + colg];
                        float x1 = acc[n8][j + 1] + a2b[l * 256 + 128 + colg + 1];
                        #pragma unroll
                        for (int c = 0; c < 3; c++) {
                            int row = c * 32 + a;
                            float p0 = x0 * acc1[c][n8][j];
                            float p1 = x1 * acc1[c][n8][j + 1];
                            split_store(sm, OFF_SVH, OFF_SVL, row, SV_S, colg, p0, p1);
                        }
                    }
            } else {
                // s_out -> HB planes
                #pragma unroll
                for (int n8 = 0; n8 < 4; n8++)
                    #pragma unroll
                    for (int j = 0; j < 4; j += 2) {
                        int a = arow + gq + ((j >> 1) << 3);
                        int col = (ng - 4) * 32 + n8 * 8 + tg * 2;
                        float x0 = acc[n8][j]     + a2b[l * 256 + col];
                        float x1 = acc[n8][j + 1] + a2b[l * 256 + col + 1];
                        split_store(sm, OFF_HBH, OFF_HBL, a, HB_S, col, x0, x1);
                    }
            }
        }
        __syncthreads();
    }

    // ---- sc[a] = dot(s[a], out_w) + ob (16 warps x 2 atoms) ----
    {
        const uint16_t* HH = (const uint16_t*)(sm + OFF_HBH);
        const uint16_t* HL = (const uint16_t*)(sm + OFF_HBL);
        float ow0 = out_w[lane], ow1 = out_w[lane + 32];
        float ow2 = out_w[lane + 64], ow3 = out_w[lane + 96];
        #pragma unroll
        for (int ai = 0; ai < 2; ai++) {
            int a = wid * 2 + ai;
            const uint16_t* rh = HH + a * HB_S;
            const uint16_t* rl = HL + a * HB_S;
            float s0 = __half2float(*(__half*)&rh[lane]) +
                       __half2float(*(__half*)&rl[lane]);
            float s1 = __half2float(*(__half*)&rh[lane + 32]) +
                       __half2float(*(__half*)&rl[lane + 32]);
            float s2 = __half2float(*(__half*)&rh[lane + 64]) +
                       __half2float(*(__half*)&rl[lane + 64]);
            float s3 = __half2float(*(__half*)&rh[lane + 96]) +
                       __half2float(*(__half*)&rl[lane + 96]);
            float acc = s0 * ow0 + s1 * ow1 + s2 * ow2 + s3 * ow3;
            #pragma unroll
            for (int off = 16; off > 0; off >>= 1)
                acc += __shfl_xor_sync(0xffffffff, acc, off);
            if (lane == 0) SCS[a] = acc + out_b[0];
        }
    }
    __syncthreads();

    // ---- masked segment sum ----
    for (int b = t; b < n_graphs; b += THREADS) {
        float acc = 0.0f;
        const float* mrow = mask + (size_t)b * n_atoms + atom0;
        for (int a = 0; a < na; a++)
            acc = fmaf(SCS[a], mrow[a], acc);
        atomicAdd(&out[b], acc);
    }
}

// ---- host ------------------------------------------------------------------
extern "C" void kernel_launch(void* const* d_in, const int* in_sizes, int n_in,
                              void* d_out, int out_size) {
    const float* s    = (const float*)d_in[0];
    const float* v    = (const float*)d_in[1];
    const float* mask = (const float*)d_in[3];
    const float* w1   = (const float*)d_in[4];
    const float* w2   = (const float*)d_in[5];
    const float* a1w  = (const float*)d_in[6];
    const float* a1b  = (const float*)d_in[7];
    const float* a2w  = (const float*)d_in[8];
    const float* a2b  = (const float*)d_in[9];
    const float* ow   = (const float*)d_in[10];
    const float* ob   = (const float*)d_in[11];
    float* out = (float*)d_out;

    const int NA = in_sizes[0] / F;
    const int L  = in_sizes[7] / F;
    const int NG = out_size;

    cudaFuncSetAttribute(fused_kernel, cudaFuncAttributeMaxDynamicSharedMemorySize,
                         SM_BYTES);

    prep1<<<(L * 8192 + 255) / 256, 256>>>(w1, w2, L);
    prep2<<<(L * 8192 + 255) / 256, 256>>>(a1w, L);
    prep3<<<(L * 8192 + 255) / 256, 256>>>(a2w, L);
    int h1 = out_size / 2, h2 = out_size - h1;
    zero_half_kernel<<<(h1 + 127) / 128, 128>>>(out, 0, h1);
    zero_half_kernel<<<(h2 + 127) / 128, 128>>>(out, h1, h2);

    int grid = (NA + TB - 1) / TB;
    fused_kernel<<<grid, THREADS, SM_BYTES>>>(s, v, mask, a1b, a2b, ow, ob, out,
                                              NA, NG, L);
}

// round 10
// speedup vs baseline: 4.3783x; 1.2219x over previous
#include <cuda_runtime.h>
#include <cuda_fp16.h>
#include <stdint.h>
#include <math.h>

#define F 128
#define TB 16            // atoms per block
#define THREADS 256
#define LMAX 2

// ---- precomputed weight fragments (uint2 = {bh0,bh1}, fp16 hi only) --------
__device__ uint2 g_B1[LMAX * 8 * 32 * 32];    // GEMM1: K=128(8 k16), N=256(32 n8)
__device__ uint2 g_B2[LMAX * 16 * 16 * 32];   // GEMM2: K=256, N=128
__device__ uint2 g_B3[LMAX * 8 * 32 * 32];    // GEMM3: K=128, N=256

// ---- helpers ---------------------------------------------------------------
__device__ __forceinline__ uint32_t pack_h(float x, float y) {
    __half hx = __float2half_rn(x), hy = __float2half_rn(y);
    uint16_t ux = *(uint16_t*)&hx, uy = *(uint16_t*)&hy;
    return (uint32_t)ux | ((uint32_t)uy << 16);
}
// fp16 split: hi = fp16(x), lo = fp16(x - hi)
__device__ __forceinline__ void split_pair(float x, float y,
                                           uint32_t& hi, uint32_t& lo) {
    __half hx = __float2half_rn(x), hy = __float2half_rn(y);
    float fx = __half2float(hx), fy = __half2float(hy);
    uint16_t ux = *(uint16_t*)&hx, uy = *(uint16_t*)&hy;
    hi = (uint32_t)ux | ((uint32_t)uy << 16);
    lo = pack_h(x - fx, y - fy);
}
__device__ __forceinline__ void mma_f16(float* d, const uint32_t* a,
                                        uint32_t b0, uint32_t b1) {
    asm volatile(
        "mma.sync.aligned.m16n8k16.row.col.f32.f16.f16.f32 "
        "{%0,%1,%2,%3}, {%4,%5,%6,%7}, {%8,%9}, {%0,%1,%2,%3};"
        : "+f"(d[0]), "+f"(d[1]), "+f"(d[2]), "+f"(d[3])
        : "r"(a[0]), "r"(a[1]), "r"(a[2]), "r"(a[3]), "r"(b0), "r"(b1));
}
__device__ __forceinline__ void ldm_x4(uint32_t* r, uint32_t addr) {
    asm volatile("ldmatrix.sync.aligned.m8n8.x4.shared.b16 {%0,%1,%2,%3}, [%4];"
        : "=r"(r[0]), "=r"(r[1]), "=r"(r[2]), "=r"(r[3]) : "r"(addr));
}
__device__ __forceinline__ uint32_t smem_u32(const void* p) {
    uint32_t a;
    asm("{ .reg .u64 t; cvta.to.shared.u64 t, %1; cvt.u32.u64 %0, t; }"
        : "=r"(a) : "l"(p));
    return a;
}

// ---- weight prep kernels (fp16 hi plane only) ------------------------------
__device__ __forceinline__ uint2 make_bfrag(float k0v, float k1v, float k8v, float k9v) {
    uint2 r;
    r.x = pack_h(k0v, k1v);
    r.y = pack_h(k8v, k9v);
    return r;
}
__global__ void prep1(const float* __restrict__ w1, const float* __restrict__ w2, int L) {
    int i = blockIdx.x * blockDim.x + threadIdx.x;
    if (i >= L * 8 * 32 * 32) return;
    int lane = i & 31, n8 = (i >> 5) & 31, k16 = (i >> 10) & 7, l = i >> 13;
    int tg = lane & 3, gq = lane >> 2;
    int n = n8 * 8 + gq, k0 = k16 * 16 + tg * 2;
    const float* W = (n < 128) ? (w1 + (size_t)l * 16384) : (w2 + (size_t)l * 16384);
    int nn = n & 127;
    g_B1[i] = make_bfrag(W[k0 * 128 + nn], W[(k0 + 1) * 128 + nn],
                         W[(k0 + 8) * 128 + nn], W[(k0 + 9) * 128 + nn]);
}
__global__ void prep2(const float* __restrict__ a1w, int L) {
    int i = blockIdx.x * blockDim.x + threadIdx.x;
    if (i >= L * 16 * 16 * 32) return;
    int lane = i & 31, n8 = (i >> 5) & 15, k16 = (i >> 9) & 15, l = i >> 13;
    int tg = lane & 3, gq = lane >> 2;
    int n = n8 * 8 + gq, k0 = k16 * 16 + tg * 2;
    const float* W = a1w + (size_t)l * 32768;
    g_B2[i] = make_bfrag(W[k0 * 128 + n], W[(k0 + 1) * 128 + n],
                         W[(k0 + 8) * 128 + n], W[(k0 + 9) * 128 + n]);
}
__global__ void prep3(const float* __restrict__ a2w, int L) {
    int i = blockIdx.x * blockDim.x + threadIdx.x;
    if (i >= L * 8 * 32 * 32) return;
    int lane = i & 31, n8 = (i >> 5) & 31, k16 = (i >> 10) & 7, l = i >> 13;
    int tg = lane & 3, gq = lane >> 2;
    int n = n8 * 8 + gq, k0 = k16 * 16 + tg * 2;
    const float* W = a2w + (size_t)l * 32768;
    g_B3[i] = make_bfrag(W[k0 * 256 + n], W[(k0 + 1) * 256 + n],
                         W[(k0 + 8) * 256 + n], W[(k0 + 9) * 256 + n]);
}

__global__ void zero_half_kernel(float* out, int base, int n) {
    int i = blockIdx.x * blockDim.x + threadIdx.x;
    if (i < n) out[base + i] = 0.0f;
}

// ---- smem layout (bytes) ----------------------------------------------------
#define SV_S 136                 // [48][128] fp16, stride 136 elems
#define HB_S 264                 // [16][256] fp16
#define AC_S 136                 // [16][128] fp16
#define OFF_SVH  0
#define OFF_SVL  (OFF_SVH + 48 * SV_S * 2)
#define OFF_HBH  (OFF_SVL + 48 * SV_S * 2)
#define OFF_HBL  (OFF_HBH + 16 * HB_S * 2)
#define OFF_ACH  (OFF_HBL + 16 * HB_S * 2)
#define OFF_ACL  (OFF_ACH + 16 * AC_S * 2)
#define OFF_SCS  (OFF_ACL + 16 * AC_S * 2)
#define SM_BYTES (OFF_SCS + 16 * 4)              // ~51.9 KB -> 2 blocks/SM

__device__ __forceinline__ uint32_t ldm_addr(uint32_t plane, int row0, int stride,
                                             int lane) {
    return plane + (uint32_t)(((row0 + (lane & 15)) * stride +
                               ((lane >> 4) << 3)) * 2);
}
__device__ __forceinline__ void split_store(char* sm, int offH, int offL,
                                            int row, int stride, int col,
                                            float x0, float x1) {
    uint32_t h, l;
    split_pair(x0, x1, h, l);
    *(uint32_t*)(sm + offH + (row * stride + col) * 2) = h;
    *(uint32_t*)(sm + offL + (row * stride + col) * 2) = l;
}

// ---- fused kernel: 8 warps (1 x 8 n-grid), TB=16, 2 blocks/SM --------------
// ng<4 warps: own v1 (GEMM1 cols 0-127) in regs, compute GEMM3 gate cols
// (128-255), gate in-register. ng>=4 warps: v2->n2, GEMM3 s cols (0-127).
__global__ void __launch_bounds__(THREADS, 2) fused_kernel(
    const float* __restrict__ s_in, const float* __restrict__ v_in,
    const float* __restrict__ mask,
    const float* __restrict__ a1b, const float* __restrict__ a2b,
    const float* __restrict__ out_w, const float* __restrict__ out_b,
    float* __restrict__ out,
    int n_atoms, int n_graphs, int n_layers)
{
    extern __shared__ char sm[];
    const int t = threadIdx.x;
    const int wid = t >> 5, lane = t & 31;
    const int tg = lane & 3, gq = lane >> 2;
    const int ng = wid;                         // 0..7
    const int atom0 = blockIdx.x * TB;
    const int na = min(TB, n_atoms - atom0);
    const uint32_t smb = smem_u32(sm);

    float* SCS = (float*)(sm + OFF_SCS);

    // ---- load + split input tiles ----
    for (int i = t; i < 48 * 64; i += THREADS) {
        int r = i >> 6, cp = i & 63;            // r = c*16 + a
        int c = r >> 4, a = r & 15;
        float2 v = make_float2(0.f, 0.f);
        if (a < na)
            v = *(const float2*)(v_in + (((size_t)(atom0 + a)) * 3 + c) * F + 2 * cp);
        split_store(sm, OFF_SVH, OFF_SVL, r, SV_S, 2 * cp, v.x, v.y);
    }
    for (int i = t; i < 16 * 64; i += THREADS) {
        int a = i >> 6, cp = i & 63;
        float2 v = make_float2(0.f, 0.f);
        if (a < na)
            v = *(const float2*)(s_in + (size_t)(atom0 + a) * F + 2 * cp);
        split_store(sm, OFF_HBH, OFF_HBL, a, HB_S, 2 * cp, v.x, v.y);
    }
    __syncthreads();

    for (int l = 0; l < n_layers; l++) {
        // GEMM1 accumulators (ng<4: v1, kept live until GEMM3; ng>=4: v2)
        float acc1[3][4][4];
        #pragma unroll
        for (int c = 0; c < 3; c++)
            #pragma unroll
            for (int n8 = 0; n8 < 4; n8++)
                #pragma unroll
                for (int j = 0; j < 4; j++) acc1[c][n8][j] = 0.0f;

        // ===== GEMM1: [48x128] @ [128x256]; k16 outer, c inner (B reuse) =====
        {
            const uint2* B1 = g_B1 + (size_t)l * 8 * 32 * 32;
            #pragma unroll
            for (int k16 = 0; k16 < 8; k16++) {
                uint32_t Ah[3][4], Al[3][4];
                #pragma unroll
                for (int c = 0; c < 3; c++) {
                    const int arow = c * 16;
                    ldm_x4(Ah[c], ldm_addr(smb + OFF_SVH, arow, SV_S, lane) + k16 * 32);
                    ldm_x4(Al[c], ldm_addr(smb + OFF_SVL, arow, SV_S, lane) + k16 * 32);
                }
                #pragma unroll
                for (int n8 = 0; n8 < 4; n8++) {
                    uint2 bb = B1[(k16 * 32 + ng * 4 + n8) * 32 + lane];
                    #pragma unroll
                    for (int c = 0; c < 3; c++) {
                        mma_f16(acc1[c][n8], Ah[c], bb.x, bb.y);
                        mma_f16(acc1[c][n8], Al[c], bb.x, bb.y);
                    }
                }
            }
            if (ng >= 4) {      // v2 -> n2 (split) into HB[:,128:256]
                #pragma unroll
                for (int n8 = 0; n8 < 4; n8++)
                    #pragma unroll
                    for (int j = 0; j < 4; j += 2) {
                        int a = gq + ((j >> 1) << 3);
                        int gcol = (ng - 4) * 32 + n8 * 8 + tg * 2;
                        float q0 = acc1[0][n8][j] * acc1[0][n8][j] +
                                   acc1[1][n8][j] * acc1[1][n8][j] +
                                   acc1[2][n8][j] * acc1[2][n8][j];
                        float q1 = acc1[0][n8][j+1] * acc1[0][n8][j+1] +
                                   acc1[1][n8][j+1] * acc1[1][n8][j+1] +
                                   acc1[2][n8][j+1] * acc1[2][n8][j+1];
                        split_store(sm, OFF_HBH, OFF_HBL, a, HB_S, 128 + gcol,
                                    sqrtf(q0), sqrtf(q1));
                    }
            }
            // ng<4: v1 stays in acc1 registers
        }
        __syncthreads();

        // ===== GEMM2: [16x256] @ [256x128] -> silu -> ACT ====================
        {
            const uint2* B2 = g_B2 + (size_t)l * 16 * 16 * 32;
            float acc[2][4];
            #pragma unroll
            for (int n8 = 0; n8 < 2; n8++)
                #pragma unroll
                for (int j = 0; j < 4; j++) acc[n8][j] = 0.0f;
            const uint32_t ah = ldm_addr(smb + OFF_HBH, 0, HB_S, lane);
            const uint32_t al = ldm_addr(smb + OFF_HBL, 0, HB_S, lane);
            #pragma unroll
            for (int k16 = 0; k16 < 16; k16++) {
                uint32_t Ah[4], Al[4];
                ldm_x4(Ah, ah + k16 * 32);
                ldm_x4(Al, al + k16 * 32);
                #pragma unroll
                for (int n8 = 0; n8 < 2; n8++) {
                    uint2 bb = B2[(k16 * 16 + ng * 2 + n8) * 32 + lane];
                    mma_f16(acc[n8], Ah, bb.x, bb.y);
                    mma_f16(acc[n8], Al, bb.x, bb.y);
                }
            }
            #pragma unroll
            for (int n8 = 0; n8 < 2; n8++)
                #pragma unroll
                for (int j = 0; j < 4; j += 2) {
                    int a = gq + ((j >> 1) << 3);
                    int col = ng * 16 + n8 * 8 + tg * 2;
                    float x0 = acc[n8][j]     + a1b[l * F + col];
                    float x1 = acc[n8][j + 1] + a1b[l * F + col + 1];
                    x0 = x0 / (1.0f + __expf(-x0));
                    x1 = x1 / (1.0f + __expf(-x1));
                    split_store(sm, OFF_ACH, OFF_ACL, a, AC_S, col, x0, x1);
                }
        }
        __syncthreads();

        // ===== GEMM3: [16x128] @ [128x256] ===================================
        // ng<4 -> gate cols 128+ng*32.. (gating in-register with acc1)
        // ng>=4 -> s cols (ng-4)*32..
        {
            const uint2* B3 = g_B3 + (size_t)l * 8 * 32 * 32;
            const int nb0 = (ng < 4) ? (16 + ng * 4) : ((ng - 4) * 4);
            float acc[4][4];
            #pragma unroll
            for (int n8 = 0; n8 < 4; n8++)
                #pragma unroll
                for (int j = 0; j < 4; j++) acc[n8][j] = 0.0f;
            const uint32_t ah = ldm_addr(smb + OFF_ACH, 0, AC_S, lane);
            const uint32_t al = ldm_addr(smb + OFF_ACL, 0, AC_S, lane);
            #pragma unroll
            for (int k16 = 0; k16 < 8; k16++) {
                uint32_t Ah[4], Al[4];
                ldm_x4(Ah, ah + k16 * 32);
                ldm_x4(Al, al + k16 * 32);
                #pragma unroll
                for (int n8 = 0; n8 < 4; n8++) {
                    uint2 bb = B3[(k16 * 32 + nb0 + n8) * 32 + lane];
                    mma_f16(acc[n8], Ah, bb.x, bb.y);
                    mma_f16(acc[n8], Al, bb.x, bb.y);
                }
            }
            if (ng < 4) {
                // gate = acc + bias; v_out = gate * v1(regs) -> SV planes
                #pragma unroll
                for (int n8 = 0; n8 < 4; n8++)
                    #pragma unroll
                    for (int j = 0; j < 4; j += 2) {
                        int a = gq + ((j >> 1) << 3);
                        int colg = ng * 32 + n8 * 8 + tg * 2;     // 0..127
                        float x0 = acc[n8][j]     + a2b[l * 256 + 128 + colg];
                        float x1 = acc[n8][j + 1] + a2b[l * 256 + 128 + colg + 1];
                        #pragma unroll
                        for (int c = 0; c < 3; c++) {
                            int row = c * 16 + a;
                            float p0 = x0 * acc1[c][n8][j];
                            float p1 = x1 * acc1[c][n8][j + 1];
                            split_store(sm, OFF_SVH, OFF_SVL, row, SV_S, colg, p0, p1);
                        }
                    }
            } else {
                // s_out -> HB planes
                #pragma unroll
                for (int n8 = 0; n8 < 4; n8++)
                    #pragma unroll
                    for (int j = 0; j < 4; j += 2) {
                        int a = gq + ((j >> 1) << 3);
                        int col = (ng - 4) * 32 + n8 * 8 + tg * 2;
                        float x0 = acc[n8][j]     + a2b[l * 256 + col];
                        float x1 = acc[n8][j + 1] + a2b[l * 256 + col + 1];
                        split_store(sm, OFF_HBH, OFF_HBL, a, HB_S, col, x0, x1);
                    }
            }
        }
        __syncthreads();
    }

    // ---- sc[a] = dot(s[a], out_w) + ob (8 warps x 2 atoms) ----
    {
        const uint16_t* HH = (const uint16_t*)(sm + OFF_HBH);
        const uint16_t* HL = (const uint16_t*)(sm + OFF_HBL);
        float ow0 = out_w[lane], ow1 = out_w[lane + 32];
        float ow2 = out_w[lane + 64], ow3 = out_w[lane + 96];
        #pragma unroll
        for (int ai = 0; ai < 2; ai++) {
            int a = wid * 2 + ai;
            const uint16_t* rh = HH + a * HB_S;
            const uint16_t* rl = HL + a * HB_S;
            float s0 = __half2float(*(__half*)&rh[lane]) +
                       __half2float(*(__half*)&rl[lane]);
            float s1 = __half2float(*(__half*)&rh[lane + 32]) +
                       __half2float(*(__half*)&rl[lane + 32]);
            float s2 = __half2float(*(__half*)&rh[lane + 64]) +
                       __half2float(*(__half*)&rl[lane + 64]);
            float s3 = __half2float(*(__half*)&rh[lane + 96]) +
                       __half2float(*(__half*)&rl[lane + 96]);
            float acc = s0 * ow0 + s1 * ow1 + s2 * ow2 + s3 * ow3;
            #pragma unroll
            for (int off = 16; off > 0; off >>= 1)
                acc += __shfl_xor_sync(0xffffffff, acc, off);
            if (lane == 0) SCS[a] = acc + out_b[0];
        }
    }
    __syncthreads();

    // ---- masked segment sum ----
    for (int b = t; b < n_graphs; b += THREADS) {
        float acc = 0.0f;
        const float* mrow = mask + (size_t)b * n_atoms + atom0;
        for (int a = 0; a < na; a++)
            acc = fmaf(SCS[a], mrow[a], acc);
        atomicAdd(&out[b], acc);
    }
}

// ---- host ------------------------------------------------------------------
extern "C" void kernel_launch(void* const* d_in, const int* in_sizes, int n_in,
                              void* d_out, int out_size) {
    const float* s    = (const float*)d_in[0];
    const float* v    = (const float*)d_in[1];
    const float* mask = (const float*)d_in[3];
    const float* w1   = (const float*)d_in[4];
    const float* w2   = (const float*)d_in[5];
    const float* a1w  = (const float*)d_in[6];
    const float* a1b  = (const float*)d_in[7];
    const float* a2w  = (const float*)d_in[8];
    const float* a2b  = (const float*)d_in[9];
    const float* ow   = (const float*)d_in[10];
    const float* ob   = (const float*)d_in[11];
    float* out = (float*)d_out;

    const int NA = in_sizes[0] / F;
    const int L  = in_sizes[7] / F;
    const int NG = out_size;

    cudaFuncSetAttribute(fused_kernel, cudaFuncAttributeMaxDynamicSharedMemorySize,
                         SM_BYTES);

    prep1<<<(L * 8192 + 255) / 256, 256>>>(w1, w2, L);
    prep2<<<(L * 8192 + 255) / 256, 256>>>(a1w, L);
    prep3<<<(L * 8192 + 255) / 256, 256>>>(a2w, L);
    int h1 = out_size / 2, h2 = out_size - h1;
    zero_half_kernel<<<(h1 + 127) / 128, 128>>>(out, 0, h1);
    zero_half_kernel<<<(h2 + 127) / 128, 128>>>(out, h1, h2);

    int grid = (NA + TB - 1) / TB;
    fused_kernel<<<grid, THREADS, SM_BYTES>>>(s, v, mask, a1b, a2b, ow, ob, out,
                                              NA, NG, L);
}

// round 11
// speedup vs baseline: 5.3748x; 1.2276x over previous
#include <cuda_runtime.h>
#include <cuda_fp16.h>
#include <stdint.h>
#include <math.h>

#define F 128
#define TB 16            // atoms per block
#define THREADS 256
#define LMAX 2

// ---- precomputed weight fragments (uint2 = {bh0,bh1}, fp16) ----------------
__device__ uint2 g_B1[LMAX * 8 * 32 * 32];    // GEMM1: K=128(8 k16), N=256(32 n8)
__device__ uint2 g_B2[LMAX * 16 * 16 * 32];   // GEMM2: K=256, N=128
__device__ uint2 g_B3[LMAX * 8 * 32 * 32];    // GEMM3: K=128, N=256

// ---- helpers ---------------------------------------------------------------
__device__ __forceinline__ uint32_t pack_h(float x, float y) {
    __half hx = __float2half_rn(x), hy = __float2half_rn(y);
    uint16_t ux = *(uint16_t*)&hx, uy = *(uint16_t*)&hy;
    return (uint32_t)ux | ((uint32_t)uy << 16);
}
__device__ __forceinline__ void mma_f16(float* d, const uint32_t* a,
                                        uint32_t b0, uint32_t b1) {
    asm volatile(
        "mma.sync.aligned.m16n8k16.row.col.f32.f16.f16.f32 "
        "{%0,%1,%2,%3}, {%4,%5,%6,%7}, {%8,%9}, {%0,%1,%2,%3};"
        : "+f"(d[0]), "+f"(d[1]), "+f"(d[2]), "+f"(d[3])
        : "r"(a[0]), "r"(a[1]), "r"(a[2]), "r"(a[3]), "r"(b0), "r"(b1));
}
__device__ __forceinline__ void ldm_x4(uint32_t* r, uint32_t addr) {
    asm volatile("ldmatrix.sync.aligned.m8n8.x4.shared.b16 {%0,%1,%2,%3}, [%4];"
        : "=r"(r[0]), "=r"(r[1]), "=r"(r[2]), "=r"(r[3]) : "r"(addr));
}
__device__ __forceinline__ uint32_t smem_u32(const void* p) {
    uint32_t a;
    asm("{ .reg .u64 t; cvta.to.shared.u64 t, %1; cvt.u32.u64 %0, t; }"
        : "=r"(a) : "l"(p));
    return a;
}

// ---- weight prep kernels ----------------------------------------------------
__device__ __forceinline__ uint2 make_bfrag(float k0v, float k1v, float k8v, float k9v) {
    uint2 r;
    r.x = pack_h(k0v, k1v);
    r.y = pack_h(k8v, k9v);
    return r;
}
__global__ void prep1(const float* __restrict__ w1, const float* __restrict__ w2, int L) {
    int i = blockIdx.x * blockDim.x + threadIdx.x;
    if (i >= L * 8 * 32 * 32) return;
    int lane = i & 31, n8 = (i >> 5) & 31, k16 = (i >> 10) & 7, l = i >> 13;
    int tg = lane & 3, gq = lane >> 2;
    int n = n8 * 8 + gq, k0 = k16 * 16 + tg * 2;
    const float* W = (n < 128) ? (w1 + (size_t)l * 16384) : (w2 + (size_t)l * 16384);
    int nn = n & 127;
    g_B1[i] = make_bfrag(W[k0 * 128 + nn], W[(k0 + 1) * 128 + nn],
                         W[(k0 + 8) * 128 + nn], W[(k0 + 9) * 128 + nn]);
}
__global__ void prep2(const float* __restrict__ a1w, int L) {
    int i = blockIdx.x * blockDim.x + threadIdx.x;
    if (i >= L * 16 * 16 * 32) return;
    int lane = i & 31, n8 = (i >> 5) & 15, k16 = (i >> 9) & 15, l = i >> 13;
    int tg = lane & 3, gq = lane >> 2;
    int n = n8 * 8 + gq, k0 = k16 * 16 + tg * 2;
    const float* W = a1w + (size_t)l * 32768;
    g_B2[i] = make_bfrag(W[k0 * 128 + n], W[(k0 + 1) * 128 + n],
                         W[(k0 + 8) * 128 + n], W[(k0 + 9) * 128 + n]);
}
__global__ void prep3(const float* __restrict__ a2w, int L) {
    int i = blockIdx.x * blockDim.x + threadIdx.x;
    if (i >= L * 8 * 32 * 32) return;
    int lane = i & 31, n8 = (i >> 5) & 31, k16 = (i >> 10) & 7, l = i >> 13;
    int tg = lane & 3, gq = lane >> 2;
    int n = n8 * 8 + gq, k0 = k16 * 16 + tg * 2;
    const float* W = a2w + (size_t)l * 32768;
    g_B3[i] = make_bfrag(W[k0 * 256 + n], W[(k0 + 1) * 256 + n],
                         W[(k0 + 8) * 256 + n], W[(k0 + 9) * 256 + n]);
}

__global__ void zero_half_kernel(float* out, int base, int n) {
    int i = blockIdx.x * blockDim.x + threadIdx.x;
    if (i < n) out[base + i] = 0.0f;
}

// ---- smem layout (bytes): single fp16 plane per tile ------------------------
#define SV_S 136                 // [48][128] fp16, stride 136 elems
#define HB_S 264                 // [16][256] fp16
#define AC_S 136                 // [16][128] fp16
#define OFF_SVH  0
#define OFF_HBH  (OFF_SVH + 48 * SV_S * 2)
#define OFF_ACH  (OFF_HBH + 16 * HB_S * 2)
#define OFF_SCS  (OFF_ACH + 16 * AC_S * 2)
#define SM_BYTES (OFF_SCS + 16 * 4)              // ~26 KB

__device__ __forceinline__ uint32_t ldm_addr(uint32_t plane, int row0, int stride,
                                             int lane) {
    return plane + (uint32_t)(((row0 + (lane & 15)) * stride +
                               ((lane >> 4) << 3)) * 2);
}
__device__ __forceinline__ void store_h(char* sm, int off, int row, int stride,
                                        int col, float x0, float x1) {
    *(uint32_t*)(sm + off + (row * stride + col) * 2) = pack_h(x0, x1);
}

// ---- fused kernel: 8 warps (1 x 8 n-grid), TB=16, 2 blocks/SM --------------
// ng<4 warps: own v1 (GEMM1 cols 0-127) in regs, compute GEMM3 gate cols
// (128-255), gate in-register. ng>=4 warps: v2->n2, GEMM3 s cols (0-127).
__global__ void __launch_bounds__(THREADS, 2) fused_kernel(
    const float* __restrict__ s_in, const float* __restrict__ v_in,
    const float* __restrict__ mask,
    const float* __restrict__ a1b, const float* __restrict__ a2b,
    const float* __restrict__ out_w, const float* __restrict__ out_b,
    float* __restrict__ out,
    int n_atoms, int n_graphs, int n_layers)
{
    extern __shared__ char sm[];
    const int t = threadIdx.x;
    const int wid = t >> 5, lane = t & 31;
    const int tg = lane & 3, gq = lane >> 2;
    const int ng = wid;                         // 0..7
    const int atom0 = blockIdx.x * TB;
    const int na = min(TB, n_atoms - atom0);
    const uint32_t smb = smem_u32(sm);

    float* SCS = (float*)(sm + OFF_SCS);

    // ---- load input tiles (fp32 -> fp16) ----
    for (int i = t; i < 48 * 64; i += THREADS) {
        int r = i >> 6, cp = i & 63;            // r = c*16 + a
        int c = r >> 4, a = r & 15;
        float2 v = make_float2(0.f, 0.f);
        if (a < na)
            v = *(const float2*)(v_in + (((size_t)(atom0 + a)) * 3 + c) * F + 2 * cp);
        store_h(sm, OFF_SVH, r, SV_S, 2 * cp, v.x, v.y);
    }
    for (int i = t; i < 16 * 64; i += THREADS) {
        int a = i >> 6, cp = i & 63;
        float2 v = make_float2(0.f, 0.f);
        if (a < na)
            v = *(const float2*)(s_in + (size_t)(atom0 + a) * F + 2 * cp);
        store_h(sm, OFF_HBH, a, HB_S, 2 * cp, v.x, v.y);
    }
    __syncthreads();

    for (int l = 0; l < n_layers; l++) {
        // GEMM1 accumulators (ng<4: v1, kept live until GEMM3; ng>=4: v2)
        float acc1[3][4][4];
        #pragma unroll
        for (int c = 0; c < 3; c++)
            #pragma unroll
            for (int n8 = 0; n8 < 4; n8++)
                #pragma unroll
                for (int j = 0; j < 4; j++) acc1[c][n8][j] = 0.0f;

        // ===== GEMM1: [48x128] @ [128x256]; k16 outer, c inner (B reuse) =====
        {
            const uint2* B1 = g_B1 + (size_t)l * 8 * 32 * 32;
            #pragma unroll
            for (int k16 = 0; k16 < 8; k16++) {
                uint32_t Ah[3][4];
                #pragma unroll
                for (int c = 0; c < 3; c++)
                    ldm_x4(Ah[c], ldm_addr(smb + OFF_SVH, c * 16, SV_S, lane) + k16 * 32);
                #pragma unroll
                for (int n8 = 0; n8 < 4; n8++) {
                    uint2 bb = B1[(k16 * 32 + ng * 4 + n8) * 32 + lane];
                    #pragma unroll
                    for (int c = 0; c < 3; c++)
                        mma_f16(acc1[c][n8], Ah[c], bb.x, bb.y);
                }
            }
            if (ng >= 4) {      // v2 -> n2 into HB[:,128:256]
                #pragma unroll
                for (int n8 = 0; n8 < 4; n8++)
                    #pragma unroll
                    for (int j = 0; j < 4; j += 2) {
                        int a = gq + ((j >> 1) << 3);
                        int gcol = (ng - 4) * 32 + n8 * 8 + tg * 2;
                        float q0 = acc1[0][n8][j] * acc1[0][n8][j] +
                                   acc1[1][n8][j] * acc1[1][n8][j] +
                                   acc1[2][n8][j] * acc1[2][n8][j];
                        float q1 = acc1[0][n8][j+1] * acc1[0][n8][j+1] +
                                   acc1[1][n8][j+1] * acc1[1][n8][j+1] +
                                   acc1[2][n8][j+1] * acc1[2][n8][j+1];
                        store_h(sm, OFF_HBH, a, HB_S, 128 + gcol,
                                sqrtf(q0), sqrtf(q1));
                    }
            }
            // ng<4: v1 stays in acc1 registers
        }
        __syncthreads();

        // ===== GEMM2: [16x256] @ [256x128] -> silu -> ACT ====================
        {
            const uint2* B2 = g_B2 + (size_t)l * 16 * 16 * 32;
            float acc[2][4];
            #pragma unroll
            for (int n8 = 0; n8 < 2; n8++)
                #pragma unroll
                for (int j = 0; j < 4; j++) acc[n8][j] = 0.0f;
            const uint32_t ah = ldm_addr(smb + OFF_HBH, 0, HB_S, lane);
            #pragma unroll
            for (int k16 = 0; k16 < 16; k16++) {
                uint32_t Ah[4];
                ldm_x4(Ah, ah + k16 * 32);
                #pragma unroll
                for (int n8 = 0; n8 < 2; n8++) {
                    uint2 bb = B2[(k16 * 16 + ng * 2 + n8) * 32 + lane];
                    mma_f16(acc[n8], Ah, bb.x, bb.y);
                }
            }
            #pragma unroll
            for (int n8 = 0; n8 < 2; n8++)
                #pragma unroll
                for (int j = 0; j < 4; j += 2) {
                    int a = gq + ((j >> 1) << 3);
                    int col = ng * 16 + n8 * 8 + tg * 2;
                    float x0 = acc[n8][j]     + a1b[l * F + col];
                    float x1 = acc[n8][j + 1] + a1b[l * F + col + 1];
                    x0 = x0 / (1.0f + __expf(-x0));
                    x1 = x1 / (1.0f + __expf(-x1));
                    store_h(sm, OFF_ACH, a, AC_S, col, x0, x1);
                }
        }
        __syncthreads();

        // ===== GEMM3: [16x128] @ [128x256] ===================================
        // ng<4 -> gate cols 128+ng*32.. (gating in-register with acc1)
        // ng>=4 -> s cols (ng-4)*32..
        {
            const uint2* B3 = g_B3 + (size_t)l * 8 * 32 * 32;
            const int nb0 = (ng < 4) ? (16 + ng * 4) : ((ng - 4) * 4);
            float acc[4][4];
            #pragma unroll
            for (int n8 = 0; n8 < 4; n8++)
                #pragma unroll
                for (int j = 0; j < 4; j++) acc[n8][j] = 0.0f;
            const uint32_t ah = ldm_addr(smb + OFF_ACH, 0, AC_S, lane);
            #pragma unroll
            for (int k16 = 0; k16 < 8; k16++) {
                uint32_t Ah[4];
                ldm_x4(Ah, ah + k16 * 32);
                #pragma unroll
                for (int n8 = 0; n8 < 4; n8++) {
                    uint2 bb = B3[(k16 * 32 + nb0 + n8) * 32 + lane];
                    mma_f16(acc[n8], Ah, bb.x, bb.y);
                }
            }
            if (ng < 4) {
                // gate = acc + bias; v_out = gate * v1(regs) -> SV plane
                #pragma unroll
                for (int n8 = 0; n8 < 4; n8++)
                    #pragma unroll
                    for (int j = 0; j < 4; j += 2) {
                        int a = gq + ((j >> 1) << 3);
                        int colg = ng * 32 + n8 * 8 + tg * 2;     // 0..127
                        float x0 = acc[n8][j]     + a2b[l * 256 + 128 + colg];
                        float x1 = acc[n8][j + 1] + a2b[l * 256 + 128 + colg + 1];
                        #pragma unroll
                        for (int c = 0; c < 3; c++) {
                            int row = c * 16 + a;
                            float p0 = x0 * acc1[c][n8][j];
                            float p1 = x1 * acc1[c][n8][j + 1];
                            store_h(sm, OFF_SVH, row, SV_S, colg, p0, p1);
                        }
                    }
            } else {
                // s_out -> HB plane
                #pragma unroll
                for (int n8 = 0; n8 < 4; n8++)
                    #pragma unroll
                    for (int j = 0; j < 4; j += 2) {
                        int a = gq + ((j >> 1) << 3);
                        int col = (ng - 4) * 32 + n8 * 8 + tg * 2;
                        float x0 = acc[n8][j]     + a2b[l * 256 + col];
                        float x1 = acc[n8][j + 1] + a2b[l * 256 + col + 1];
                        store_h(sm, OFF_HBH, a, HB_S, col, x0, x1);
                    }
            }
        }
        __syncthreads();
    }

    // ---- sc[a] = dot(s[a], out_w) + ob (8 warps x 2 atoms) ----
    {
        const uint16_t* HH = (const uint16_t*)(sm + OFF_HBH);
        float ow0 = out_w[lane], ow1 = out_w[lane + 32];
        float ow2 = out_w[lane + 64], ow3 = out_w[lane + 96];
        #pragma unroll
        for (int ai = 0; ai < 2; ai++) {
            int a = wid * 2 + ai;
            const uint16_t* rh = HH + a * HB_S;
            float s0 = __half2float(*(__half*)&rh[lane]);
            float s1 = __half2float(*(__half*)&rh[lane + 32]);
            float s2 = __half2float(*(__half*)&rh[lane + 64]);
            float s3 = __half2float(*(__half*)&rh[lane + 96]);
            float acc = s0 * ow0 + s1 * ow1 + s2 * ow2 + s3 * ow3;
            #pragma unroll
            for (int off = 16; off > 0; off >>= 1)
                acc += __shfl_xor_sync(0xffffffff, acc, off);
            if (lane == 0) SCS[a] = acc + out_b[0];
        }
    }
    __syncthreads();

    // ---- masked segment sum ----
    for (int b = t; b < n_graphs; b += THREADS) {
        float acc = 0.0f;
        const float* mrow = mask + (size_t)b * n_atoms + atom0;
        for (int a = 0; a < na; a++)
            acc = fmaf(SCS[a], mrow[a], acc);
        atomicAdd(&out[b], acc);
    }
}

// ---- host ------------------------------------------------------------------
extern "C" void kernel_launch(void* const* d_in, const int* in_sizes, int n_in,
                              void* d_out, int out_size) {
    const float* s    = (const float*)d_in[0];
    const float* v    = (const float*)d_in[1];
    const float* mask = (const float*)d_in[3];
    const float* w1   = (const float*)d_in[4];
    const float* w2   = (const float*)d_in[5];
    const float* a1w  = (const float*)d_in[6];
    const float* a1b  = (const float*)d_in[7];
    const float* a2w  = (const float*)d_in[8];
    const float* a2b  = (const float*)d_in[9];
    const float* ow   = (const float*)d_in[10];
    const float* ob   = (const float*)d_in[11];
    float* out = (float*)d_out;

    const int NA = in_sizes[0] / F;
    const int L  = in_sizes[7] / F;
    const int NG = out_size;

    cudaFuncSetAttribute(fused_kernel, cudaFuncAttributeMaxDynamicSharedMemorySize,
                         SM_BYTES);

    prep1<<<(L * 8192 + 255) / 256, 256>>>(w1, w2, L);
    prep2<<<(L * 8192 + 255) / 256, 256>>>(a1w, L);
    prep3<<<(L * 8192 + 255) / 256, 256>>>(a2w, L);
    int h1 = out_size / 2, h2 = out_size - h1;
    zero_half_kernel<<<(h1 + 127) / 128, 128>>>(out, 0, h1);
    zero_half_kernel<<<(h2 + 127) / 128, 128>>>(out, h1, h2);

    int grid = (NA + TB - 1) / TB;
    fused_kernel<<<grid, THREADS, SM_BYTES>>>(s, v, mask, a1b, a2b, ow, ob, out,
                                              NA, NG, L);
}

// round 12
// speedup vs baseline: 5.4535x; 1.0146x over previous
#include <cuda_runtime.h>
#include <cuda_fp16.h>
#include <stdint.h>
#include <math.h>

#define F 128
#define TB 16            // atoms per block
#define THREADS 512
#define LMAX 2

// ---- precomputed weight fragments (uint2 = {bh0,bh1}, fp16) ----------------
__device__ uint2 g_B1[LMAX * 8 * 32 * 32];    // GEMM1: K=128(8 k16), N=256(32 n8)
__device__ uint2 g_B2[LMAX * 16 * 16 * 32];   // GEMM2: K=256, N=128
__device__ uint2 g_B3[LMAX * 8 * 32 * 32];    // GEMM3: K=128, N=256

// ---- helpers ---------------------------------------------------------------
__device__ __forceinline__ uint32_t pack_h(float x, float y) {
    __half hx = __float2half_rn(x), hy = __float2half_rn(y);
    uint16_t ux = *(uint16_t*)&hx, uy = *(uint16_t*)&hy;
    return (uint32_t)ux | ((uint32_t)uy << 16);
}
__device__ __forceinline__ void mma_f16(float* d, const uint32_t* a,
                                        uint32_t b0, uint32_t b1) {
    asm volatile(
        "mma.sync.aligned.m16n8k16.row.col.f32.f16.f16.f32 "
        "{%0,%1,%2,%3}, {%4,%5,%6,%7}, {%8,%9}, {%0,%1,%2,%3};"
        : "+f"(d[0]), "+f"(d[1]), "+f"(d[2]), "+f"(d[3])
        : "r"(a[0]), "r"(a[1]), "r"(a[2]), "r"(a[3]), "r"(b0), "r"(b1));
}
__device__ __forceinline__ void ldm_x4(uint32_t* r, uint32_t addr) {
    asm volatile("ldmatrix.sync.aligned.m8n8.x4.shared.b16 {%0,%1,%2,%3}, [%4];"
        : "=r"(r[0]), "=r"(r[1]), "=r"(r[2]), "=r"(r[3]) : "r"(addr));
}
__device__ __forceinline__ uint32_t smem_u32(const void* p) {
    uint32_t a;
    asm("{ .reg .u64 t; cvta.to.shared.u64 t, %1; cvt.u32.u64 %0, t; }"
        : "=r"(a) : "l"(p));
    return a;
}

// ---- weight prep kernels ----------------------------------------------------
__device__ __forceinline__ uint2 make_bfrag(float k0v, float k1v, float k8v, float k9v) {
    uint2 r;
    r.x = pack_h(k0v, k1v);
    r.y = pack_h(k8v, k9v);
    return r;
}
__global__ void prep1(const float* __restrict__ w1, const float* __restrict__ w2, int L) {
    int i = blockIdx.x * blockDim.x + threadIdx.x;
    if (i >= L * 8 * 32 * 32) return;
    int lane = i & 31, n8 = (i >> 5) & 31, k16 = (i >> 10) & 7, l = i >> 13;
    int tg = lane & 3, gq = lane >> 2;
    int n = n8 * 8 + gq, k0 = k16 * 16 + tg * 2;
    const float* W = (n < 128) ? (w1 + (size_t)l * 16384) : (w2 + (size_t)l * 16384);
    int nn = n & 127;
    g_B1[i] = make_bfrag(W[k0 * 128 + nn], W[(k0 + 1) * 128 + nn],
                         W[(k0 + 8) * 128 + nn], W[(k0 + 9) * 128 + nn]);
}
__global__ void prep2(const float* __restrict__ a1w, int L) {
    int i = blockIdx.x * blockDim.x + threadIdx.x;
    if (i >= L * 16 * 16 * 32) return;
    int lane = i & 31, n8 = (i >> 5) & 15, k16 = (i >> 9) & 15, l = i >> 13;
    int tg = lane & 3, gq = lane >> 2;
    int n = n8 * 8 + gq, k0 = k16 * 16 + tg * 2;
    const float* W = a1w + (size_t)l * 32768;
    g_B2[i] = make_bfrag(W[k0 * 128 + n], W[(k0 + 1) * 128 + n],
                         W[(k0 + 8) * 128 + n], W[(k0 + 9) * 128 + n]);
}
__global__ void prep3(const float* __restrict__ a2w, int L) {
    int i = blockIdx.x * blockDim.x + threadIdx.x;
    if (i >= L * 8 * 32 * 32) return;
    int lane = i & 31, n8 = (i >> 5) & 31, k16 = (i >> 10) & 7, l = i >> 13;
    int tg = lane & 3, gq = lane >> 2;
    int n = n8 * 8 + gq, k0 = k16 * 16 + tg * 2;
    const float* W = a2w + (size_t)l * 32768;
    g_B3[i] = make_bfrag(W[k0 * 256 + n], W[(k0 + 1) * 256 + n],
                         W[(k0 + 8) * 256 + n], W[(k0 + 9) * 256 + n]);
}

__global__ void zero_half_kernel(float* out, int base, int n) {
    int i = blockIdx.x * blockDim.x + threadIdx.x;
    if (i < n) out[base + i] = 0.0f;
}

// ---- smem layout (bytes): single fp16 plane per tile ------------------------
#define SV_S 136                 // [48][128] fp16, stride 136 elems
#define HB_S 264                 // [16][256] fp16
#define AC_S 136                 // [16][128] fp16
#define OFF_SVH  0
#define OFF_HBH  (OFF_SVH + 48 * SV_S * 2)
#define OFF_ACH  (OFF_HBH + 16 * HB_S * 2)
#define OFF_SCS  (OFF_ACH + 16 * AC_S * 2)
#define SM_BYTES (OFF_SCS + 16 * 4)              // ~26 KB

__device__ __forceinline__ uint32_t ldm_addr(uint32_t plane, int row0, int stride,
                                             int lane) {
    return plane + (uint32_t)(((row0 + (lane & 15)) * stride +
                               ((lane >> 4) << 3)) * 2);
}
__device__ __forceinline__ void store_h(char* sm, int off, int row, int stride,
                                        int col, float x0, float x1) {
    *(uint32_t*)(sm + off + (row * stride + col) * 2) = pack_h(x0, x1);
}

// ---- fused kernel: 16 warps (1 x 16 n-grid), TB=16, 2 blocks/SM ------------
// Each warp owns a 16-col N-slice (2 n8) in GEMM1/3, 1 n8 in GEMM2.
// ng<8: v1 slice in regs, GEMM3 gate cols 128+ng*16, gate in-register.
// ng>=8: v2 slice -> n2, GEMM3 s cols (ng-8)*16.
__global__ void __launch_bounds__(THREADS, 2) fused_kernel(
    const float* __restrict__ s_in, const float* __restrict__ v_in,
    const float* __restrict__ mask,
    const float* __restrict__ a1b, const float* __restrict__ a2b,
    const float* __restrict__ out_w, const float* __restrict__ out_b,
    float* __restrict__ out,
    int n_atoms, int n_graphs, int n_layers)
{
    extern __shared__ char sm[];
    const int t = threadIdx.x;
    const int wid = t >> 5, lane = t & 31;
    const int tg = lane & 3, gq = lane >> 2;
    const int ng = wid;                         // 0..15
    const int atom0 = blockIdx.x * TB;
    const int na = min(TB, n_atoms - atom0);
    const uint32_t smb = smem_u32(sm);

    float* SCS = (float*)(sm + OFF_SCS);

    // ---- load input tiles (fp32 -> fp16) ----
    for (int i = t; i < 48 * 64; i += THREADS) {
        int r = i >> 6, cp = i & 63;            // r = c*16 + a
        int c = r >> 4, a = r & 15;
        float2 v = make_float2(0.f, 0.f);
        if (a < na)
            v = *(const float2*)(v_in + (((size_t)(atom0 + a)) * 3 + c) * F + 2 * cp);
        store_h(sm, OFF_SVH, r, SV_S, 2 * cp, v.x, v.y);
    }
    for (int i = t; i < 16 * 64; i += THREADS) {
        int a = i >> 6, cp = i & 63;
        float2 v = make_float2(0.f, 0.f);
        if (a < na)
            v = *(const float2*)(s_in + (size_t)(atom0 + a) * F + 2 * cp);
        store_h(sm, OFF_HBH, a, HB_S, 2 * cp, v.x, v.y);
    }
    __syncthreads();

    for (int l = 0; l < n_layers; l++) {
        // GEMM1 accumulators: [c][n8 in {0,1}][frag]
        float acc1[3][2][4];
        #pragma unroll
        for (int c = 0; c < 3; c++)
            #pragma unroll
            for (int n8 = 0; n8 < 2; n8++)
                #pragma unroll
                for (int j = 0; j < 4; j++) acc1[c][n8][j] = 0.0f;

        // ===== GEMM1: [48x128] @ [128x256]; k16 outer, c inner (B reuse) =====
        {
            const uint2* B1 = g_B1 + (size_t)l * 8 * 32 * 32;
            #pragma unroll
            for (int k16 = 0; k16 < 8; k16++) {
                uint32_t Ah[3][4];
                #pragma unroll
                for (int c = 0; c < 3; c++)
                    ldm_x4(Ah[c], ldm_addr(smb + OFF_SVH, c * 16, SV_S, lane) + k16 * 32);
                #pragma unroll
                for (int n8 = 0; n8 < 2; n8++) {
                    uint2 bb = B1[(k16 * 32 + ng * 2 + n8) * 32 + lane];
                    #pragma unroll
                    for (int c = 0; c < 3; c++)
                        mma_f16(acc1[c][n8], Ah[c], bb.x, bb.y);
                }
            }
            if (ng >= 8) {      // v2 -> n2 into HB[:,128:256]
                #pragma unroll
                for (int n8 = 0; n8 < 2; n8++)
                    #pragma unroll
                    for (int j = 0; j < 4; j += 2) {
                        int a = gq + ((j >> 1) << 3);
                        int gcol = (ng - 8) * 16 + n8 * 8 + tg * 2;
                        float q0 = acc1[0][n8][j] * acc1[0][n8][j] +
                                   acc1[1][n8][j] * acc1[1][n8][j] +
                                   acc1[2][n8][j] * acc1[2][n8][j];
                        float q1 = acc1[0][n8][j+1] * acc1[0][n8][j+1] +
                                   acc1[1][n8][j+1] * acc1[1][n8][j+1] +
                                   acc1[2][n8][j+1] * acc1[2][n8][j+1];
                        store_h(sm, OFF_HBH, a, HB_S, 128 + gcol,
                                sqrtf(q0), sqrtf(q1));
                    }
            }
            // ng<8: v1 stays in acc1 registers
        }
        __syncthreads();

        // ===== GEMM2: [16x256] @ [256x128] -> silu -> ACT ====================
        {
            const uint2* B2 = g_B2 + (size_t)l * 16 * 16 * 32;
            float acc[4];
            #pragma unroll
            for (int j = 0; j < 4; j++) acc[j] = 0.0f;
            const uint32_t ah = ldm_addr(smb + OFF_HBH, 0, HB_S, lane);
            #pragma unroll
            for (int k16 = 0; k16 < 16; k16++) {
                uint32_t Ah[4];
                ldm_x4(Ah, ah + k16 * 32);
                uint2 bb = B2[(k16 * 16 + ng) * 32 + lane];
                mma_f16(acc, Ah, bb.x, bb.y);
            }
            #pragma unroll
            for (int j = 0; j < 4; j += 2) {
                int a = gq + ((j >> 1) << 3);
                int col = ng * 8 + tg * 2;
                float x0 = acc[j]     + a1b[l * F + col];
                float x1 = acc[j + 1] + a1b[l * F + col + 1];
                x0 = x0 / (1.0f + __expf(-x0));
                x1 = x1 / (1.0f + __expf(-x1));
                store_h(sm, OFF_ACH, a, AC_S, col, x0, x1);
            }
        }
        __syncthreads();

        // ===== GEMM3: [16x128] @ [128x256] ===================================
        // ng<8 -> gate cols 128+ng*16 (gating in-register with acc1)
        // ng>=8 -> s cols (ng-8)*16
        {
            const uint2* B3 = g_B3 + (size_t)l * 8 * 32 * 32;
            const int nb0 = (ng < 8) ? (16 + ng * 2) : ((ng - 8) * 2);
            float acc[2][4];
            #pragma unroll
            for (int n8 = 0; n8 < 2; n8++)
                #pragma unroll
                for (int j = 0; j < 4; j++) acc[n8][j] = 0.0f;
            const uint32_t ah = ldm_addr(smb + OFF_ACH, 0, AC_S, lane);
            #pragma unroll
            for (int k16 = 0; k16 < 8; k16++) {
                uint32_t Ah[4];
                ldm_x4(Ah, ah + k16 * 32);
                #pragma unroll
                for (int n8 = 0; n8 < 2; n8++) {
                    uint2 bb = B3[(k16 * 32 + nb0 + n8) * 32 + lane];
                    mma_f16(acc[n8], Ah, bb.x, bb.y);
                }
            }
            if (ng < 8) {
                // gate = acc + bias; v_out = gate * v1(regs) -> SV plane
                #pragma unroll
                for (int n8 = 0; n8 < 2; n8++)
                    #pragma unroll
                    for (int j = 0; j < 4; j += 2) {
                        int a = gq + ((j >> 1) << 3);
                        int colg = ng * 16 + n8 * 8 + tg * 2;     // 0..127
                        float x0 = acc[n8][j]     + a2b[l * 256 + 128 + colg];
                        float x1 = acc[n8][j + 1] + a2b[l * 256 + 128 + colg + 1];
                        #pragma unroll
                        for (int c = 0; c < 3; c++) {
                            int row = c * 16 + a;
                            float p0 = x0 * acc1[c][n8][j];
                            float p1 = x1 * acc1[c][n8][j + 1];
                            store_h(sm, OFF_SVH, row, SV_S, colg, p0, p1);
                        }
                    }
            } else {
                // s_out -> HB plane
                #pragma unroll
                for (int n8 = 0; n8 < 2; n8++)
                    #pragma unroll
                    for (int j = 0; j < 4; j += 2) {
                        int a = gq + ((j >> 1) << 3);
                        int col = (ng - 8) * 16 + n8 * 8 + tg * 2;
                        float x0 = acc[n8][j]     + a2b[l * 256 + col];
                        float x1 = acc[n8][j + 1] + a2b[l * 256 + col + 1];
                        store_h(sm, OFF_HBH, a, HB_S, col, x0, x1);
                    }
            }
        }
        __syncthreads();
    }

    // ---- sc[a] = dot(s[a], out_w) + ob (16 warps x 1 atom) ----
    {
        const uint16_t* HH = (const uint16_t*)(sm + OFF_HBH);
        float ow0 = out_w[lane], ow1 = out_w[lane + 32];
        float ow2 = out_w[lane + 64], ow3 = out_w[lane + 96];
        int a = wid;
        const uint16_t* rh = HH + a * HB_S;
        float s0 = __half2float(*(__half*)&rh[lane]);
        float s1 = __half2float(*(__half*)&rh[lane + 32]);
        float s2 = __half2float(*(__half*)&rh[lane + 64]);
        float s3 = __half2float(*(__half*)&rh[lane + 96]);
        float acc = s0 * ow0 + s1 * ow1 + s2 * ow2 + s3 * ow3;
        #pragma unroll
        for (int off = 16; off > 0; off >>= 1)
            acc += __shfl_xor_sync(0xffffffff, acc, off);
        if (lane == 0) SCS[a] = acc + out_b[0];
    }
    __syncthreads();

    // ---- masked segment sum ----
    for (int b = t; b < n_graphs; b += THREADS) {
        float acc = 0.0f;
        const float* mrow = mask + (size_t)b * n_atoms + atom0;
        for (int a = 0; a < na; a++)
            acc = fmaf(SCS[a], mrow[a], acc);
        atomicAdd(&out[b], acc);
    }
}

// ---- host ------------------------------------------------------------------
extern "C" void kernel_launch(void* const* d_in, const int* in_sizes, int n_in,
                              void* d_out, int out_size) {
    const float* s    = (const float*)d_in[0];
    const float* v    = (const float*)d_in[1];
    const float* mask = (const float*)d_in[3];
    const float* w1   = (const float*)d_in[4];
    const float* w2   = (const float*)d_in[5];
    const float* a1w  = (const float*)d_in[6];
    const float* a1b  = (const float*)d_in[7];
    const float* a2w  = (const float*)d_in[8];
    const float* a2b  = (const float*)d_in[9];
    const float* ow   = (const float*)d_in[10];
    const float* ob   = (const float*)d_in[11];
    float* out = (float*)d_out;

    const int NA = in_sizes[0] / F;
    const int L  = in_sizes[7] / F;
    const int NG = out_size;

    cudaFuncSetAttribute(fused_kernel, cudaFuncAttributeMaxDynamicSharedMemorySize,
                         SM_BYTES);

    prep1<<<(L * 8192 + 255) / 256, 256>>>(w1, w2, L);
    prep2<<<(L * 8192 + 255) / 256, 256>>>(a1w, L);
    prep3<<<(L * 8192 + 255) / 256, 256>>>(a2w, L);
    int h1 = out_size / 2, h2 = out_size - h1;
    zero_half_kernel<<<(h1 + 127) / 128, 128>>>(out, 0, h1);
    zero_half_kernel<<<(h2 + 127) / 128, 128>>>(out, h1, h2);

    int grid = (NA + TB - 1) / TB;
    fused_kernel<<<grid, THREADS, SM_BYTES>>>(s, v, mask, a1b, a2b, ow, ob, out,
                                              NA, NG, L);
}